// round 1
// baseline (speedup 1.0000x reference)
#include <cuda_runtime.h>
#include <cuda_bf16.h>
#include <cstdint>

// Problem constants
#define E_DIM   1024
#define H_NUM   16
#define D_DIM   64
#define B_NUM   4
#define S_LEN   2048
#define R_RANK  8
#define M_TOK   (B_NUM * S_LEN)      // 8192
#define N_QKV   (3 * E_DIM)          // 3072
#define LORA_SCALING 2.0f
#define ATTN_SCALE   0.125f          // D^-0.5

// ---------------------------------------------------------------------------
// Scratch (device globals: allocation-free per harness rules)
// ---------------------------------------------------------------------------
__device__ float g_Wqkv[N_QKV * E_DIM];     // fused QKV weight   (12 MB)
__device__ float g_Wproj[E_DIM * E_DIM];    // fused proj weight  (4 MB)
__device__ float g_qkv[(size_t)M_TOK * N_QKV];   // qkv activations (96 MB)
__device__ float g_att[(size_t)M_TOK * E_DIM];   // attention out   (32 MB)

// ---------------------------------------------------------------------------
// Kernel 1: fold LoRA into dense weight:  out = W + 2 * (Bm @ Am)
//   W, out: [Nrows, 1024] row-major; Am: [8,1024]; Bm: [Nrows, 8]
// ---------------------------------------------------------------------------
__global__ void fuse_w(const float* __restrict__ W, const float* __restrict__ Am,
                       const float* __restrict__ Bm, float* __restrict__ out,
                       int Nrows)
{
    int idx = blockIdx.x * 256 + threadIdx.x;
    if (idx >= Nrows * 1024) return;
    int n = idx >> 10;
    int k = idx & 1023;
    float acc = W[idx];
#pragma unroll
    for (int r = 0; r < R_RANK; r++)
        acc = fmaf(LORA_SCALING * Bm[n * R_RANK + r], Am[r * 1024 + k], acc);
    out[idx] = acc;
}

// ---------------------------------------------------------------------------
// Kernel 2/4: SGEMM  C[M,N] = A[M,K] @ W[N,K]^T (+ bias)
//   128x128 tile, BK=16, 256 threads, 8x8 per-thread register tile
// ---------------------------------------------------------------------------
template <bool BIAS>
__global__ __launch_bounds__(256)
void sgemm_nt(const float* __restrict__ A, const float* __restrict__ W,
              const float* __restrict__ bias, float* __restrict__ C,
              int Mn, int Nn, int Kn)
{
    __shared__ float As[16][128];
    __shared__ float Ws[16][128];

    const int t  = threadIdx.x;
    const int tx = t & 15;
    const int ty = t >> 4;
    const int row0 = blockIdx.y << 7;
    const int col0 = blockIdx.x << 7;

    // loader mapping: 64 B contiguous per 4 lanes, 2 row passes
    const int lr = t >> 2;         // 0..63
    const int lk = (t & 3) << 2;   // 0,4,8,12

    const float* Ap0 = A + (size_t)(row0 + lr) * Kn + lk;
    const float* Ap1 = Ap0 + (size_t)64 * Kn;
    const float* Wp0 = W + (size_t)(col0 + lr) * Kn + lk;
    const float* Wp1 = Wp0 + (size_t)64 * Kn;

    float acc[8][8];
#pragma unroll
    for (int i = 0; i < 8; i++)
#pragma unroll
        for (int j = 0; j < 8; j++) acc[i][j] = 0.0f;

    for (int k0 = 0; k0 < Kn; k0 += 16) {
        float4 a0 = *(const float4*)(Ap0 + k0);
        float4 a1 = *(const float4*)(Ap1 + k0);
        float4 w0 = *(const float4*)(Wp0 + k0);
        float4 w1 = *(const float4*)(Wp1 + k0);

        __syncthreads();
        As[lk + 0][lr] = a0.x; As[lk + 1][lr] = a0.y;
        As[lk + 2][lr] = a0.z; As[lk + 3][lr] = a0.w;
        As[lk + 0][lr + 64] = a1.x; As[lk + 1][lr + 64] = a1.y;
        As[lk + 2][lr + 64] = a1.z; As[lk + 3][lr + 64] = a1.w;
        Ws[lk + 0][lr] = w0.x; Ws[lk + 1][lr] = w0.y;
        Ws[lk + 2][lr] = w0.z; Ws[lk + 3][lr] = w0.w;
        Ws[lk + 0][lr + 64] = w1.x; Ws[lk + 1][lr + 64] = w1.y;
        Ws[lk + 2][lr + 64] = w1.z; Ws[lk + 3][lr + 64] = w1.w;
        __syncthreads();

#pragma unroll
        for (int kk = 0; kk < 16; kk++) {
            float af[8], wf[8];
            *(float4*)(af)     = *(const float4*)(&As[kk][ty * 8]);
            *(float4*)(af + 4) = *(const float4*)(&As[kk][ty * 8 + 4]);
            *(float4*)(wf)     = *(const float4*)(&Ws[kk][tx * 8]);
            *(float4*)(wf + 4) = *(const float4*)(&Ws[kk][tx * 8 + 4]);
#pragma unroll
            for (int i = 0; i < 8; i++)
#pragma unroll
                for (int j = 0; j < 8; j++)
                    acc[i][j] = fmaf(af[i], wf[j], acc[i][j]);
        }
    }

#pragma unroll
    for (int i = 0; i < 8; i++) {
        int r = row0 + ty * 8 + i;
#pragma unroll
        for (int j = 0; j < 8; j += 4) {
            int c = col0 + tx * 8 + j;
            float4 v;
            v.x = acc[i][j];     v.y = acc[i][j + 1];
            v.z = acc[i][j + 2]; v.w = acc[i][j + 3];
            if (BIAS) {
                v.x += bias[c];     v.y += bias[c + 1];
                v.z += bias[c + 2]; v.w += bias[c + 3];
            }
            *(float4*)(&C[(size_t)r * Nn + c]) = v;
        }
    }
}

// ---------------------------------------------------------------------------
// Kernel 3: causal flash attention (fp32, online softmax)
//   grid = (32 q-tiles, 64 bh), block = 128 threads
//   qkv layout: row (b*S+s), col = c*1024 + h*64 + d   (c in {q,k,v})
//   out layout: [B*S, 1024] with col = h*64 + d
// ---------------------------------------------------------------------------
#define ATTN_SMEM_FLOATS (64*64 + 64*65 + 64*65 + 64*64)  // Qs, Ks, Ps, Vs
#define ATTN_SMEM_BYTES  (ATTN_SMEM_FLOATS * 4)

__global__ __launch_bounds__(128)
void attn_kernel(const float* __restrict__ qkv, float* __restrict__ out)
{
    extern __shared__ float sm[];
    float* Qs = sm;                  // [64][64]  (d-major, broadcast reads)
    float* Ks = Qs + 64 * 64;        // [64][65]  (d-major, padded)
    float* Ps = Ks + 64 * 65;        // [64][65]  (n-major, padded)
    float* Vs = Ps + 64 * 65;        // [64][64]  (n-major)
#define QS(d, m) Qs[(d) * 64 + (m)]
#define KS(d, n) Ks[(d) * 65 + (n)]
#define PS(n, m) Ps[(n) * 65 + (m)]
#define VS(n, d) Vs[(n) * 64 + (d)]

    const int t   = threadIdx.x;
    const int tx  = t & 15;          // 0..15 : column group (4 cols)
    const int ty  = t >> 4;          // 0..7  : row group   (8 rows)
    const int tx4 = tx * 4;
    const int ty8 = ty * 8;

    const int qi = blockIdx.x;       // q tile index (0..31)
    const int bh = blockIdx.y;       // 0..63
    const int b  = bh >> 4;
    const int h  = bh & 15;

    const float* qbase = qkv + (size_t)b * S_LEN * 3072 + h * 64;
    const float* kbase = qbase + 1024;
    const float* vbase = qbase + 2048;

    // Load Q tile (transposed store; one-time, conflicts don't matter)
    const int dd = tx * 4;
    {
        const float* qp = qbase + (size_t)(qi * 64) * 3072 + dd;
#pragma unroll
        for (int r = t >> 4; r < 64; r += 8) {
            float4 q4 = *(const float4*)(qp + (size_t)r * 3072);
            QS(dd + 0, r) = q4.x; QS(dd + 1, r) = q4.y;
            QS(dd + 2, r) = q4.z; QS(dd + 3, r) = q4.w;
        }
    }

    float O[8][4];
    float rmax[8], rsum[8];
#pragma unroll
    for (int i = 0; i < 8; i++) {
        rmax[i] = -1e30f; rsum[i] = 0.0f;
#pragma unroll
        for (int j = 0; j < 4; j++) O[i][j] = 0.0f;
    }

    for (int j = 0; j <= qi; j++) {
        __syncthreads();   // prev iter reads done (also covers Q store on iter 0)

        // Load K (transposed) + V (direct) tile j
        const float* kp = kbase + (size_t)(j * 64) * 3072 + dd;
        const float* vp = vbase + (size_t)(j * 64) * 3072 + dd;
#pragma unroll
        for (int r = t >> 4; r < 64; r += 8) {
            float4 k4 = *(const float4*)(kp + (size_t)r * 3072);
            KS(dd + 0, r) = k4.x; KS(dd + 1, r) = k4.y;
            KS(dd + 2, r) = k4.z; KS(dd + 3, r) = k4.w;
            float4 v4 = *(const float4*)(vp + (size_t)r * 3072);
            *(float4*)&VS(r, dd) = v4;
        }
        __syncthreads();

        // S = Q @ K^T   (8x4 per thread over 64-deep d)
        float sacc[8][4];
#pragma unroll
        for (int i = 0; i < 8; i++)
#pragma unroll
            for (int jj = 0; jj < 4; jj++) sacc[i][jj] = 0.0f;

#pragma unroll 4
        for (int d = 0; d < 64; d++) {
            float qf[8], kf[4];
#pragma unroll
            for (int i = 0; i < 8; i++)  qf[i]  = QS(d, ty8 + i);
#pragma unroll
            for (int jj = 0; jj < 4; jj++) kf[jj] = KS(d, tx4 + jj);
#pragma unroll
            for (int i = 0; i < 8; i++)
#pragma unroll
                for (int jj = 0; jj < 4; jj++)
                    sacc[i][jj] = fmaf(qf[i], kf[jj], sacc[i][jj]);
        }

        // scale + causal mask (diagonal tile only)
        const bool diag = (j == qi);
#pragma unroll
        for (int i = 0; i < 8; i++)
#pragma unroll
            for (int jj = 0; jj < 4; jj++) {
                float s = sacc[i][jj] * ATTN_SCALE;
                if (diag && (tx4 + jj > ty8 + i)) s = -1e30f;
                sacc[i][jj] = s;
            }

        // online softmax per row (reduce over 16-lane tx group)
#pragma unroll
        for (int i = 0; i < 8; i++) {
            float m = fmaxf(fmaxf(sacc[i][0], sacc[i][1]),
                            fmaxf(sacc[i][2], sacc[i][3]));
#pragma unroll
            for (int off = 1; off < 16; off <<= 1)
                m = fmaxf(m, __shfl_xor_sync(0xffffffffu, m, off));
            float nm = fmaxf(rmax[i], m);
            float corr = __expf(rmax[i] - nm);
            rmax[i] = nm;
            rsum[i] *= corr;
#pragma unroll
            for (int jj = 0; jj < 4; jj++) O[i][jj] *= corr;
            float ls = 0.0f;
#pragma unroll
            for (int jj = 0; jj < 4; jj++) {
                float p = __expf(sacc[i][jj] - nm);
                sacc[i][jj] = p;
                ls += p;
            }
#pragma unroll
            for (int off = 1; off < 16; off <<= 1)
                ls += __shfl_xor_sync(0xffffffffu, ls, off);
            rsum[i] += ls;
        }

        // write P (n-major) for PV gemm
#pragma unroll
        for (int i = 0; i < 8; i++)
#pragma unroll
            for (int jj = 0; jj < 4; jj++)
                PS(tx4 + jj, ty8 + i) = sacc[i][jj];
        __syncthreads();

        // O += P @ V
#pragma unroll 4
        for (int n = 0; n < 64; n++) {
            float pf[8], vf[4];
#pragma unroll
            for (int i = 0; i < 8; i++) pf[i] = PS(n, ty8 + i);
            *(float4*)vf = *(const float4*)&VS(n, tx4);
#pragma unroll
            for (int i = 0; i < 8; i++)
#pragma unroll
                for (int jj = 0; jj < 4; jj++)
                    O[i][jj] = fmaf(pf[i], vf[jj], O[i][jj]);
        }
    }

    // epilogue: normalize + store [B*S, 1024]
    float* obase = out + ((size_t)b * S_LEN + qi * 64) * 1024 + h * 64;
#pragma unroll
    for (int i = 0; i < 8; i++) {
        float inv = 1.0f / rsum[i];
        float4 v;
        v.x = O[i][0] * inv; v.y = O[i][1] * inv;
        v.z = O[i][2] * inv; v.w = O[i][3] * inv;
        *(float4*)(obase + (size_t)(ty8 + i) * 1024 + tx4) = v;
    }
#undef QS
#undef KS
#undef PS
#undef VS
}

// ---------------------------------------------------------------------------
// Launcher
// ---------------------------------------------------------------------------
extern "C" void kernel_launch(void* const* d_in, const int* in_sizes, int n_in,
                              void* d_out, int out_size)
{
    const float* x     = (const float*)d_in[0];
    // d_in[1] = mask: deterministic causal tril -> implemented analytically
    const float* Wqkv  = (const float*)d_in[2];
    const float* Wproj = (const float*)d_in[3];
    const float* bproj = (const float*)d_in[4];
    const float* Aqkv  = (const float*)d_in[5];
    const float* Bqkv  = (const float*)d_in[6];
    const float* Aproj = (const float*)d_in[7];
    const float* Bproj = (const float*)d_in[8];

    float *wq, *wp, *qkv, *att;
    cudaGetSymbolAddress((void**)&wq,  g_Wqkv);
    cudaGetSymbolAddress((void**)&wp,  g_Wproj);
    cudaGetSymbolAddress((void**)&qkv, g_qkv);
    cudaGetSymbolAddress((void**)&att, g_att);

    // 1) fold LoRA into dense weights
    fuse_w<<<(N_QKV * E_DIM + 255) / 256, 256>>>(Wqkv, Aqkv, Bqkv, wq, N_QKV);
    fuse_w<<<(E_DIM * E_DIM + 255) / 256, 256>>>(Wproj, Aproj, Bproj, wp, E_DIM);

    // 2) qkv = x @ Wqkv_eff^T
    sgemm_nt<false><<<dim3(N_QKV / 128, M_TOK / 128), 256>>>(
        x, wq, nullptr, qkv, M_TOK, N_QKV, E_DIM);

    // 3) causal flash attention
    cudaFuncSetAttribute(attn_kernel, cudaFuncAttributeMaxDynamicSharedMemorySize,
                         ATTN_SMEM_BYTES);
    attn_kernel<<<dim3(S_LEN / 64, B_NUM * H_NUM), 128, ATTN_SMEM_BYTES>>>(qkv, att);

    // 4) out = att @ Wproj_eff^T + bproj
    sgemm_nt<true><<<dim3(E_DIM / 128, M_TOK / 128), 256>>>(
        att, wp, bproj, (float*)d_out, M_TOK, E_DIM, E_DIM);
}

// round 3
// speedup vs baseline: 1.5987x; 1.5987x over previous
#include <cuda_runtime.h>
#include <cstdint>

// Problem constants
#define E_DIM   1024
#define H_NUM   16
#define B_NUM   4
#define S_LEN   2048
#define R_RANK  8
#define M_TOK   (B_NUM * S_LEN)      // 8192
#define N_QKV   (3 * E_DIM)          // 3072
#define LORA_SCALING 2.0f
#define ATTN_SCALE   0.125f          // D^-0.5

// ---------------------------------------------------------------------------
// Scratch (device globals: allocation-free per harness rules)
// ---------------------------------------------------------------------------
__device__ float g_Wqkv[N_QKV * E_DIM];          // fused QKV weight   (12 MB)
__device__ float g_Wproj[E_DIM * E_DIM];         // fused proj weight  (4 MB)
__device__ float g_qkv[(size_t)M_TOK * N_QKV];   // qkv activations (96 MB)
__device__ float g_att[(size_t)M_TOK * E_DIM];   // attention out   (32 MB)

// ---------------------------------------------------------------------------
// helpers
// ---------------------------------------------------------------------------
__device__ __forceinline__ uint32_t f2tf32(float f) {
    uint32_t o;
    asm("cvt.rna.tf32.f32 %0, %1;" : "=r"(o) : "f"(f));
    return o;
}
__device__ __forceinline__ void mma_tf32(float& c0, float& c1, float& c2, float& c3,
                                         uint32_t a0, uint32_t a1, uint32_t a2, uint32_t a3,
                                         uint32_t b0, uint32_t b1) {
    asm volatile(
        "mma.sync.aligned.m16n8k8.row.col.f32.tf32.tf32.f32 "
        "{%0,%1,%2,%3}, {%4,%5,%6,%7}, {%8,%9}, {%0,%1,%2,%3};"
        : "+f"(c0), "+f"(c1), "+f"(c2), "+f"(c3)
        : "r"(a0), "r"(a1), "r"(a2), "r"(a3), "r"(b0), "r"(b1));
}

// ---------------------------------------------------------------------------
// Kernel 1: fold LoRA into dense weight:  out = W + 2 * (Bm @ Am)
// ---------------------------------------------------------------------------
__global__ void fuse_w(const float* __restrict__ W, const float* __restrict__ Am,
                       const float* __restrict__ Bm, float* __restrict__ out,
                       int Nrows)
{
    int idx = blockIdx.x * 256 + threadIdx.x;
    if (idx >= Nrows * 1024) return;
    int n = idx >> 10;
    int k = idx & 1023;
    float acc = W[idx];
#pragma unroll
    for (int r = 0; r < R_RANK; r++)
        acc = fmaf(LORA_SCALING * Bm[n * R_RANK + r], Am[r * 1024 + k], acc);
    out[idx] = acc;
}

// ---------------------------------------------------------------------------
// tf32 tensor-core GEMM:  C[M,N] = A[M,K] @ W[N,K]^T (+ bias)
//   tile 128x128, BK=16, 256 threads (8 warps: 2x4, 64x32 per warp)
//   mma.sync.m16n8k8.tf32 ; tf32 conversion (rna) at STS time
// ---------------------------------------------------------------------------
template <bool BIAS>
__global__ __launch_bounds__(256)
void gemm_mma(const float* __restrict__ A, const float* __restrict__ W,
              const float* __restrict__ bias, float* __restrict__ C,
              int Kn, int Nn)
{
    __shared__ uint32_t As[2][128][20];   // [buf][m][k] tf32 bits, pad 20
    __shared__ uint32_t Ws[2][128][20];   // [buf][n][k]

    const int t    = threadIdx.x;
    const int wid  = t >> 5;
    const int lid  = t & 31;
    const int gid  = lid >> 2;           // 0..7
    const int tg   = lid & 3;            // 0..3
    const int wm   = (wid >> 2) * 64;    // warp M offset (0,64)
    const int wn   = (wid & 3) * 32;     // warp N offset (0..96)
    const int row0 = blockIdx.y << 7;
    const int col0 = blockIdx.x << 7;

    // loader mapping: 4 threads per row, 16B each, rows lr and lr+64
    const int lr = t >> 2;               // 0..63
    const int lk = (t & 3) << 2;         // 0,4,8,12
    const float* Ap0 = A + (size_t)(row0 + lr) * Kn + lk;
    const float* Ap1 = Ap0 + (size_t)64 * Kn;
    const float* Wp0 = W + (size_t)(col0 + lr) * Kn + lk;
    const float* Wp1 = Wp0 + (size_t)64 * Kn;

    float acc[4][4][4];                  // [mt][nt][4]
#pragma unroll
    for (int i = 0; i < 4; i++)
#pragma unroll
        for (int j = 0; j < 4; j++)
#pragma unroll
            for (int r = 0; r < 4; r++) acc[i][j][r] = 0.0f;

    const int nkt = Kn >> 4;             // 64 K-tiles

    // preload stage 0
    {
        float4 a0 = *(const float4*)(Ap0);
        float4 a1 = *(const float4*)(Ap1);
        float4 w0 = *(const float4*)(Wp0);
        float4 w1 = *(const float4*)(Wp1);
        As[0][lr][lk+0] = f2tf32(a0.x); As[0][lr][lk+1] = f2tf32(a0.y);
        As[0][lr][lk+2] = f2tf32(a0.z); As[0][lr][lk+3] = f2tf32(a0.w);
        As[0][lr+64][lk+0] = f2tf32(a1.x); As[0][lr+64][lk+1] = f2tf32(a1.y);
        As[0][lr+64][lk+2] = f2tf32(a1.z); As[0][lr+64][lk+3] = f2tf32(a1.w);
        Ws[0][lr][lk+0] = f2tf32(w0.x); Ws[0][lr][lk+1] = f2tf32(w0.y);
        Ws[0][lr][lk+2] = f2tf32(w0.z); Ws[0][lr][lk+3] = f2tf32(w0.w);
        Ws[0][lr+64][lk+0] = f2tf32(w1.x); Ws[0][lr+64][lk+1] = f2tf32(w1.y);
        Ws[0][lr+64][lk+2] = f2tf32(w1.z); Ws[0][lr+64][lk+3] = f2tf32(w1.w);
    }
    __syncthreads();

    for (int kt = 0; kt < nkt; kt++) {
        const int cur = kt & 1, nxt = cur ^ 1;

        // prefetch next tile (LDG early, consumed after compute)
        float4 pa0, pa1, pw0, pw1;
        if (kt + 1 < nkt) {
            const int k0 = (kt + 1) << 4;
            pa0 = *(const float4*)(Ap0 + k0);
            pa1 = *(const float4*)(Ap1 + k0);
            pw0 = *(const float4*)(Wp0 + k0);
            pw1 = *(const float4*)(Wp1 + k0);
        }

        // compute on cur: 2 k-chunks of 8
#pragma unroll
        for (int kc = 0; kc < 16; kc += 8) {
            uint32_t af[4][4], bf[4][2];
#pragma unroll
            for (int mt = 0; mt < 4; mt++) {
                const int r = wm + mt * 16 + gid;
                af[mt][0] = As[cur][r][kc + tg];
                af[mt][1] = As[cur][r + 8][kc + tg];
                af[mt][2] = As[cur][r][kc + tg + 4];
                af[mt][3] = As[cur][r + 8][kc + tg + 4];
            }
#pragma unroll
            for (int nt = 0; nt < 4; nt++) {
                const int n = wn + nt * 8 + gid;
                bf[nt][0] = Ws[cur][n][kc + tg];
                bf[nt][1] = Ws[cur][n][kc + tg + 4];
            }
#pragma unroll
            for (int mt = 0; mt < 4; mt++)
#pragma unroll
                for (int nt = 0; nt < 4; nt++)
                    mma_tf32(acc[mt][nt][0], acc[mt][nt][1],
                             acc[mt][nt][2], acc[mt][nt][3],
                             af[mt][0], af[mt][1], af[mt][2], af[mt][3],
                             bf[nt][0], bf[nt][1]);
        }

        // store prefetched tile into nxt (safe: nxt last read at kt-1, synced)
        if (kt + 1 < nkt) {
            As[nxt][lr][lk+0] = f2tf32(pa0.x); As[nxt][lr][lk+1] = f2tf32(pa0.y);
            As[nxt][lr][lk+2] = f2tf32(pa0.z); As[nxt][lr][lk+3] = f2tf32(pa0.w);
            As[nxt][lr+64][lk+0] = f2tf32(pa1.x); As[nxt][lr+64][lk+1] = f2tf32(pa1.y);
            As[nxt][lr+64][lk+2] = f2tf32(pa1.z); As[nxt][lr+64][lk+3] = f2tf32(pa1.w);
            Ws[nxt][lr][lk+0] = f2tf32(pw0.x); Ws[nxt][lr][lk+1] = f2tf32(pw0.y);
            Ws[nxt][lr][lk+2] = f2tf32(pw0.z); Ws[nxt][lr][lk+3] = f2tf32(pw0.w);
            Ws[nxt][lr+64][lk+0] = f2tf32(pw1.x); Ws[nxt][lr+64][lk+1] = f2tf32(pw1.y);
            Ws[nxt][lr+64][lk+2] = f2tf32(pw1.z); Ws[nxt][lr+64][lk+3] = f2tf32(pw1.w);
        }
        __syncthreads();
    }

    // epilogue: c0,c1 at (row gid, col 2*tg), c2,c3 at row gid+8
#pragma unroll
    for (int mt = 0; mt < 4; mt++) {
        const int r = row0 + wm + mt * 16 + gid;
#pragma unroll
        for (int nt = 0; nt < 4; nt++) {
            const int c = col0 + wn + nt * 8 + tg * 2;
            float2 v0, v1;
            v0.x = acc[mt][nt][0]; v0.y = acc[mt][nt][1];
            v1.x = acc[mt][nt][2]; v1.y = acc[mt][nt][3];
            if (BIAS) {
                float b0 = bias[c], b1 = bias[c + 1];
                v0.x += b0; v0.y += b1;
                v1.x += b0; v1.y += b1;
            }
            *(float2*)(&C[(size_t)r * Nn + c])       = v0;
            *(float2*)(&C[(size_t)(r + 8) * Nn + c]) = v1;
        }
    }
}

// ---------------------------------------------------------------------------
// Kernel 3: causal flash attention (fp32, online softmax)
// ---------------------------------------------------------------------------
#define ATTN_SMEM_FLOATS (64*64 + 64*65 + 64*65 + 64*64)
#define ATTN_SMEM_BYTES  (ATTN_SMEM_FLOATS * 4)

__global__ __launch_bounds__(128)
void attn_kernel(const float* __restrict__ qkv, float* __restrict__ out)
{
    extern __shared__ float sm[];
    float* Qs = sm;
    float* Ks = Qs + 64 * 64;
    float* Ps = Ks + 64 * 65;
    float* Vs = Ps + 64 * 65;
#define QS(d, m) Qs[(d) * 64 + (m)]
#define KS(d, n) Ks[(d) * 65 + (n)]
#define PS(n, m) Ps[(n) * 65 + (m)]
#define VS(n, d) Vs[(n) * 64 + (d)]

    const int t   = threadIdx.x;
    const int tx  = t & 15;
    const int ty  = t >> 4;
    const int tx4 = tx * 4;
    const int ty8 = ty * 8;

    const int qi = blockIdx.x;
    const int bh = blockIdx.y;
    const int b  = bh >> 4;
    const int h  = bh & 15;

    const float* qbase = qkv + (size_t)b * S_LEN * 3072 + h * 64;
    const float* kbase = qbase + 1024;
    const float* vbase = qbase + 2048;

    const int dd = tx * 4;
    {
        const float* qp = qbase + (size_t)(qi * 64) * 3072 + dd;
#pragma unroll
        for (int r = t >> 4; r < 64; r += 8) {
            float4 q4 = *(const float4*)(qp + (size_t)r * 3072);
            QS(dd + 0, r) = q4.x; QS(dd + 1, r) = q4.y;
            QS(dd + 2, r) = q4.z; QS(dd + 3, r) = q4.w;
        }
    }

    float O[8][4];
    float rmax[8], rsum[8];
#pragma unroll
    for (int i = 0; i < 8; i++) {
        rmax[i] = -1e30f; rsum[i] = 0.0f;
#pragma unroll
        for (int j = 0; j < 4; j++) O[i][j] = 0.0f;
    }

    for (int j = 0; j <= qi; j++) {
        __syncthreads();

        const float* kp = kbase + (size_t)(j * 64) * 3072 + dd;
        const float* vp = vbase + (size_t)(j * 64) * 3072 + dd;
#pragma unroll
        for (int r = t >> 4; r < 64; r += 8) {
            float4 k4 = *(const float4*)(kp + (size_t)r * 3072);
            KS(dd + 0, r) = k4.x; KS(dd + 1, r) = k4.y;
            KS(dd + 2, r) = k4.z; KS(dd + 3, r) = k4.w;
            float4 v4 = *(const float4*)(vp + (size_t)r * 3072);
            *(float4*)&VS(r, dd) = v4;
        }
        __syncthreads();

        float sacc[8][4];
#pragma unroll
        for (int i = 0; i < 8; i++)
#pragma unroll
            for (int jj = 0; jj < 4; jj++) sacc[i][jj] = 0.0f;

#pragma unroll 4
        for (int d = 0; d < 64; d++) {
            float qf[8], kf[4];
#pragma unroll
            for (int i = 0; i < 8; i++)  qf[i]  = QS(d, ty8 + i);
#pragma unroll
            for (int jj = 0; jj < 4; jj++) kf[jj] = KS(d, tx4 + jj);
#pragma unroll
            for (int i = 0; i < 8; i++)
#pragma unroll
                for (int jj = 0; jj < 4; jj++)
                    sacc[i][jj] = fmaf(qf[i], kf[jj], sacc[i][jj]);
        }

        const bool diag = (j == qi);
#pragma unroll
        for (int i = 0; i < 8; i++)
#pragma unroll
            for (int jj = 0; jj < 4; jj++) {
                float s = sacc[i][jj] * ATTN_SCALE;
                if (diag && (tx4 + jj > ty8 + i)) s = -1e30f;
                sacc[i][jj] = s;
            }

#pragma unroll
        for (int i = 0; i < 8; i++) {
            float m = fmaxf(fmaxf(sacc[i][0], sacc[i][1]),
                            fmaxf(sacc[i][2], sacc[i][3]));
#pragma unroll
            for (int off = 1; off < 16; off <<= 1)
                m = fmaxf(m, __shfl_xor_sync(0xffffffffu, m, off));
            float nm = fmaxf(rmax[i], m);
            float corr = __expf(rmax[i] - nm);
            rmax[i] = nm;
            rsum[i] *= corr;
#pragma unroll
            for (int jj = 0; jj < 4; jj++) O[i][jj] *= corr;
            float ls = 0.0f;
#pragma unroll
            for (int jj = 0; jj < 4; jj++) {
                float p = __expf(sacc[i][jj] - nm);
                sacc[i][jj] = p;
                ls += p;
            }
#pragma unroll
            for (int off = 1; off < 16; off <<= 1)
                ls += __shfl_xor_sync(0xffffffffu, ls, off);
            rsum[i] += ls;
        }

#pragma unroll
        for (int i = 0; i < 8; i++)
#pragma unroll
            for (int jj = 0; jj < 4; jj++)
                PS(tx4 + jj, ty8 + i) = sacc[i][jj];
        __syncthreads();

#pragma unroll 4
        for (int n = 0; n < 64; n++) {
            float pf[8], vf[4];
#pragma unroll
            for (int i = 0; i < 8; i++) pf[i] = PS(n, ty8 + i);
            *(float4*)vf = *(const float4*)&VS(n, tx4);
#pragma unroll
            for (int i = 0; i < 8; i++)
#pragma unroll
                for (int jj = 0; jj < 4; jj++)
                    O[i][jj] = fmaf(pf[i], vf[jj], O[i][jj]);
        }
    }

    float* obase = out + ((size_t)b * S_LEN + qi * 64) * 1024 + h * 64;
#pragma unroll
    for (int i = 0; i < 8; i++) {
        float inv = 1.0f / rsum[i];
        float4 v;
        v.x = O[i][0] * inv; v.y = O[i][1] * inv;
        v.z = O[i][2] * inv; v.w = O[i][3] * inv;
        *(float4*)(obase + (size_t)(ty8 + i) * 1024 + tx4) = v;
    }
#undef QS
#undef KS
#undef PS
#undef VS
}

// ---------------------------------------------------------------------------
// Launcher
// ---------------------------------------------------------------------------
extern "C" void kernel_launch(void* const* d_in, const int* in_sizes, int n_in,
                              void* d_out, int out_size)
{
    const float* x     = (const float*)d_in[0];
    // d_in[1] = mask: deterministic causal tril -> handled analytically
    const float* Wqkv  = (const float*)d_in[2];
    const float* Wproj = (const float*)d_in[3];
    const float* bproj = (const float*)d_in[4];
    const float* Aqkv  = (const float*)d_in[5];
    const float* Bqkv  = (const float*)d_in[6];
    const float* Aproj = (const float*)d_in[7];
    const float* Bproj = (const float*)d_in[8];

    float *wq, *wp, *qkv, *att;
    cudaGetSymbolAddress((void**)&wq,  g_Wqkv);
    cudaGetSymbolAddress((void**)&wp,  g_Wproj);
    cudaGetSymbolAddress((void**)&qkv, g_qkv);
    cudaGetSymbolAddress((void**)&att, g_att);

    cudaFuncSetAttribute(attn_kernel,
                         cudaFuncAttributeMaxDynamicSharedMemorySize, ATTN_SMEM_BYTES);

    // 1) fold LoRA into dense weights
    fuse_w<<<(N_QKV * E_DIM + 255) / 256, 256>>>(Wqkv, Aqkv, Bqkv, wq, N_QKV);
    fuse_w<<<(E_DIM * E_DIM + 255) / 256, 256>>>(Wproj, Aproj, Bproj, wp, E_DIM);

    // 2) qkv = x @ Wqkv_eff^T   (tf32 tensor cores)
    gemm_mma<false><<<dim3(N_QKV / 128, M_TOK / 128), 256>>>(
        x, wq, nullptr, qkv, E_DIM, N_QKV);

    // 3) causal flash attention
    attn_kernel<<<dim3(S_LEN / 64, B_NUM * H_NUM), 128, ATTN_SMEM_BYTES>>>(qkv, att);

    // 4) out = att @ Wproj_eff^T + bproj   (tf32 tensor cores)
    gemm_mma<true><<<dim3(E_DIM / 128, M_TOK / 128), 256>>>(
        att, wp, bproj, (float*)d_out, E_DIM, E_DIM);
}

// round 5
// speedup vs baseline: 2.0479x; 1.2810x over previous
#include <cuda_runtime.h>
#include <cstdint>

// Problem constants
#define E_DIM   1024
#define H_NUM   16
#define B_NUM   4
#define S_LEN   2048
#define R_RANK  8
#define M_TOK   (B_NUM * S_LEN)      // 8192
#define N_QKV   (3 * E_DIM)          // 3072
#define LORA_SCALING 2.0f
#define ATTN_SCALE   0.125f          // D^-0.5

// ---------------------------------------------------------------------------
// Scratch (device globals: allocation-free per harness rules)
// ---------------------------------------------------------------------------
__device__ float g_Wqkv[N_QKV * E_DIM];          // fused QKV weight   (12 MB)
__device__ float g_Wproj[E_DIM * E_DIM];         // fused proj weight  (4 MB)
__device__ float g_qkv[(size_t)M_TOK * N_QKV];   // qkv activations (96 MB)
__device__ float g_att[(size_t)M_TOK * E_DIM];   // attention out   (32 MB)

// ---------------------------------------------------------------------------
// helpers
// ---------------------------------------------------------------------------
__device__ __forceinline__ uint32_t f2tf32(float f) {
    uint32_t o;
    asm("cvt.rna.tf32.f32 %0, %1;" : "=r"(o) : "f"(f));
    return o;
}
__device__ __forceinline__ void mma_tf32(float& c0, float& c1, float& c2, float& c3,
                                         uint32_t a0, uint32_t a1, uint32_t a2, uint32_t a3,
                                         uint32_t b0, uint32_t b1) {
    asm volatile(
        "mma.sync.aligned.m16n8k8.row.col.f32.tf32.tf32.f32 "
        "{%0,%1,%2,%3}, {%4,%5,%6,%7}, {%8,%9}, {%0,%1,%2,%3};"
        : "+f"(c0), "+f"(c1), "+f"(c2), "+f"(c3)
        : "r"(a0), "r"(a1), "r"(a2), "r"(a3), "r"(b0), "r"(b1));
}

// ---------------------------------------------------------------------------
// Kernel 1: fold LoRA into dense weight:  out = W + 2 * (Bm @ Am)
// ---------------------------------------------------------------------------
__global__ void fuse_w(const float* __restrict__ W, const float* __restrict__ Am,
                       const float* __restrict__ Bm, float* __restrict__ out,
                       int Nrows)
{
    int idx = blockIdx.x * 256 + threadIdx.x;
    if (idx >= Nrows * 1024) return;
    int n = idx >> 10;
    int k = idx & 1023;
    float acc = W[idx];
#pragma unroll
    for (int r = 0; r < R_RANK; r++)
        acc = fmaf(LORA_SCALING * Bm[n * R_RANK + r], Am[r * 1024 + k], acc);
    out[idx] = acc;
}

// ---------------------------------------------------------------------------
// tf32 tensor-core GEMM:  C[M,N] = A[M,K] @ W[N,K]^T (+ bias)
//   tile 128x128, BK=16, 256 threads (8 warps: 2x4, 64x32 per warp)
// ---------------------------------------------------------------------------
template <bool BIAS>
__global__ __launch_bounds__(256)
void gemm_mma(const float* __restrict__ A, const float* __restrict__ W,
              const float* __restrict__ bias, float* __restrict__ C,
              int Kn, int Nn)
{
    __shared__ uint32_t As[2][128][20];
    __shared__ uint32_t Ws[2][128][20];

    const int t    = threadIdx.x;
    const int wid  = t >> 5;
    const int lid  = t & 31;
    const int gid  = lid >> 2;
    const int tg   = lid & 3;
    const int wm   = (wid >> 2) * 64;
    const int wn   = (wid & 3) * 32;
    const int row0 = blockIdx.y << 7;
    const int col0 = blockIdx.x << 7;

    const int lr = t >> 2;
    const int lk = (t & 3) << 2;
    const float* Ap0 = A + (size_t)(row0 + lr) * Kn + lk;
    const float* Ap1 = Ap0 + (size_t)64 * Kn;
    const float* Wp0 = W + (size_t)(col0 + lr) * Kn + lk;
    const float* Wp1 = Wp0 + (size_t)64 * Kn;

    float acc[4][4][4];
#pragma unroll
    for (int i = 0; i < 4; i++)
#pragma unroll
        for (int j = 0; j < 4; j++)
#pragma unroll
            for (int r = 0; r < 4; r++) acc[i][j][r] = 0.0f;

    const int nkt = Kn >> 4;

    {
        float4 a0 = *(const float4*)(Ap0);
        float4 a1 = *(const float4*)(Ap1);
        float4 w0 = *(const float4*)(Wp0);
        float4 w1 = *(const float4*)(Wp1);
        As[0][lr][lk+0] = f2tf32(a0.x); As[0][lr][lk+1] = f2tf32(a0.y);
        As[0][lr][lk+2] = f2tf32(a0.z); As[0][lr][lk+3] = f2tf32(a0.w);
        As[0][lr+64][lk+0] = f2tf32(a1.x); As[0][lr+64][lk+1] = f2tf32(a1.y);
        As[0][lr+64][lk+2] = f2tf32(a1.z); As[0][lr+64][lk+3] = f2tf32(a1.w);
        Ws[0][lr][lk+0] = f2tf32(w0.x); Ws[0][lr][lk+1] = f2tf32(w0.y);
        Ws[0][lr][lk+2] = f2tf32(w0.z); Ws[0][lr][lk+3] = f2tf32(w0.w);
        Ws[0][lr+64][lk+0] = f2tf32(w1.x); Ws[0][lr+64][lk+1] = f2tf32(w1.y);
        Ws[0][lr+64][lk+2] = f2tf32(w1.z); Ws[0][lr+64][lk+3] = f2tf32(w1.w);
    }
    __syncthreads();

    for (int kt = 0; kt < nkt; kt++) {
        const int cur = kt & 1, nxt = cur ^ 1;

        float4 pa0, pa1, pw0, pw1;
        if (kt + 1 < nkt) {
            const int k0 = (kt + 1) << 4;
            pa0 = *(const float4*)(Ap0 + k0);
            pa1 = *(const float4*)(Ap1 + k0);
            pw0 = *(const float4*)(Wp0 + k0);
            pw1 = *(const float4*)(Wp1 + k0);
        }

#pragma unroll
        for (int kc = 0; kc < 16; kc += 8) {
            uint32_t af[4][4], bf[4][2];
#pragma unroll
            for (int mt = 0; mt < 4; mt++) {
                const int r = wm + mt * 16 + gid;
                af[mt][0] = As[cur][r][kc + tg];
                af[mt][1] = As[cur][r + 8][kc + tg];
                af[mt][2] = As[cur][r][kc + tg + 4];
                af[mt][3] = As[cur][r + 8][kc + tg + 4];
            }
#pragma unroll
            for (int nt = 0; nt < 4; nt++) {
                const int n = wn + nt * 8 + gid;
                bf[nt][0] = Ws[cur][n][kc + tg];
                bf[nt][1] = Ws[cur][n][kc + tg + 4];
            }
#pragma unroll
            for (int mt = 0; mt < 4; mt++)
#pragma unroll
                for (int nt = 0; nt < 4; nt++)
                    mma_tf32(acc[mt][nt][0], acc[mt][nt][1],
                             acc[mt][nt][2], acc[mt][nt][3],
                             af[mt][0], af[mt][1], af[mt][2], af[mt][3],
                             bf[nt][0], bf[nt][1]);
        }

        if (kt + 1 < nkt) {
            As[nxt][lr][lk+0] = f2tf32(pa0.x); As[nxt][lr][lk+1] = f2tf32(pa0.y);
            As[nxt][lr][lk+2] = f2tf32(pa0.z); As[nxt][lr][lk+3] = f2tf32(pa0.w);
            As[nxt][lr+64][lk+0] = f2tf32(pa1.x); As[nxt][lr+64][lk+1] = f2tf32(pa1.y);
            As[nxt][lr+64][lk+2] = f2tf32(pa1.z); As[nxt][lr+64][lk+3] = f2tf32(pa1.w);
            Ws[nxt][lr][lk+0] = f2tf32(pw0.x); Ws[nxt][lr][lk+1] = f2tf32(pw0.y);
            Ws[nxt][lr][lk+2] = f2tf32(pw0.z); Ws[nxt][lr][lk+3] = f2tf32(pw0.w);
            Ws[nxt][lr+64][lk+0] = f2tf32(pw1.x); Ws[nxt][lr+64][lk+1] = f2tf32(pw1.y);
            Ws[nxt][lr+64][lk+2] = f2tf32(pw1.z); Ws[nxt][lr+64][lk+3] = f2tf32(pw1.w);
        }
        __syncthreads();
    }

#pragma unroll
    for (int mt = 0; mt < 4; mt++) {
        const int r = row0 + wm + mt * 16 + gid;
#pragma unroll
        for (int nt = 0; nt < 4; nt++) {
            const int c = col0 + wn + nt * 8 + tg * 2;
            float2 v0, v1;
            v0.x = acc[mt][nt][0]; v0.y = acc[mt][nt][1];
            v1.x = acc[mt][nt][2]; v1.y = acc[mt][nt][3];
            if (BIAS) {
                float b0 = bias[c], b1 = bias[c + 1];
                v0.x += b0; v0.y += b1;
                v1.x += b0; v1.y += b1;
            }
            *(float2*)(&C[(size_t)r * Nn + c])       = v0;
            *(float2*)(&C[(size_t)(r + 8) * Nn + c]) = v1;
        }
    }
}

// ---------------------------------------------------------------------------
// Kernel 3: causal flash attention on tensor cores (tf32 mma, fp32 softmax)
//   128 threads (4 warps); 64x64 tiles; warp w owns q-rows [16w,16w+16)
// ---------------------------------------------------------------------------
#define AQ_STR 68
#define AK_STR 72
#define ATTN2_SMEM_BYTES ((64*AQ_STR + 64*AK_STR + 64*AK_STR + 64*AQ_STR) * 4)

__global__ __launch_bounds__(128)
void attn_mma(const float* __restrict__ qkv, float* __restrict__ out)
{
    extern __shared__ uint32_t smu[];
    uint32_t* Qs = smu;
    uint32_t* Ks = Qs + 64 * AQ_STR;
    uint32_t* Vs = Ks + 64 * AK_STR;
    uint32_t* Ps = Vs + 64 * AK_STR;

    const int t   = threadIdx.x;
    const int w   = t >> 5;
    const int lid = t & 31;
    const int gid = lid >> 2;
    const int tg  = lid & 3;

    const int qi = (int)gridDim.x - 1 - (int)blockIdx.x;  // long blocks first
    const int bh = blockIdx.y;
    const int b  = bh >> 4;
    const int h  = bh & 15;

    const float* qbase = qkv + (size_t)b * S_LEN * 3072 + h * 64;
    const float* kbase = qbase + 1024;
    const float* vbase = qbase + 2048;

    // load Q tile (scale folded, tf32), layout [q][d]
    const int lr = t >> 4;            // 0..7  (row offset within each 8-row pass)
    const int dd = (t & 15) * 4;      // 0..60
    {
        const float* qp = qbase + (size_t)(qi * 64 + lr) * 3072 + dd;
#pragma unroll
        for (int p = 0; p < 8; p++) {
            int r = lr + p * 8;
            float4 q4 = *(const float4*)(qp + (size_t)(p * 8) * 3072);
            uint32_t* dst = &Qs[r * AQ_STR + dd];
            dst[0] = f2tf32(q4.x * ATTN_SCALE);
            dst[1] = f2tf32(q4.y * ATTN_SCALE);
            dst[2] = f2tf32(q4.z * ATTN_SCALE);
            dst[3] = f2tf32(q4.w * ATTN_SCALE);
        }
    }

    const int R0 = w * 16 + gid;      // local q row of c0,c1
    float O[8][4];
    float rmax0 = -1e30f, rmax1 = -1e30f, rsum0 = 0.0f, rsum1 = 0.0f;
#pragma unroll
    for (int i = 0; i < 8; i++)
#pragma unroll
        for (int j = 0; j < 4; j++) O[i][j] = 0.0f;

    for (int j = 0; j <= qi; j++) {
        __syncthreads();   // prior PV reads of Vs done (and Q store on j=0)

        // load K (transposed -> [d][k]) and V ([k][d]) tiles
        const float* kp = kbase + (size_t)(j * 64 + lr) * 3072 + dd;
        const float* vp = vbase + (size_t)(j * 64 + lr) * 3072 + dd;
#pragma unroll
        for (int p = 0; p < 8; p++) {
            int r = lr + p * 8;
            float4 k4 = *(const float4*)(kp + (size_t)(p * 8) * 3072);
            Ks[(dd + 0) * AK_STR + r] = f2tf32(k4.x);
            Ks[(dd + 1) * AK_STR + r] = f2tf32(k4.y);
            Ks[(dd + 2) * AK_STR + r] = f2tf32(k4.z);
            Ks[(dd + 3) * AK_STR + r] = f2tf32(k4.w);
            float4 v4 = *(const float4*)(vp + (size_t)(p * 8) * 3072);
            uint32_t* dst = &Vs[r * AK_STR + dd];
            dst[0] = f2tf32(v4.x); dst[1] = f2tf32(v4.y);
            dst[2] = f2tf32(v4.z); dst[3] = f2tf32(v4.w);
        }
        __syncthreads();

        // ---- S = Q @ K^T : 8 k-steps (d), 8 n-frags (k cols) ----
        float sacc[8][4];
#pragma unroll
        for (int i = 0; i < 8; i++)
#pragma unroll
            for (int jj = 0; jj < 4; jj++) sacc[i][jj] = 0.0f;

#pragma unroll
        for (int kk = 0; kk < 8; kk++) {
            const int kb = kk * 8;
            uint32_t a0 = Qs[R0 * AQ_STR + kb + tg];
            uint32_t a1 = Qs[(R0 + 8) * AQ_STR + kb + tg];
            uint32_t a2 = Qs[R0 * AQ_STR + kb + tg + 4];
            uint32_t a3 = Qs[(R0 + 8) * AQ_STR + kb + tg + 4];
#pragma unroll
            for (int nt = 0; nt < 8; nt++) {
                uint32_t b0 = Ks[(kb + tg) * AK_STR + nt * 8 + gid];
                uint32_t b1 = Ks[(kb + tg + 4) * AK_STR + nt * 8 + gid];
                mma_tf32(sacc[nt][0], sacc[nt][1], sacc[nt][2], sacc[nt][3],
                         a0, a1, a2, a3, b0, b1);
            }
        }

        // causal mask on diagonal tile
        if (j == qi) {
#pragma unroll
            for (int nt = 0; nt < 8; nt++) {
                int c0 = nt * 8 + 2 * tg;
                if (c0 > R0)         sacc[nt][0] = -1e30f;
                if (c0 + 1 > R0)     sacc[nt][1] = -1e30f;
                if (c0 > R0 + 8)     sacc[nt][2] = -1e30f;
                if (c0 + 1 > R0 + 8) sacc[nt][3] = -1e30f;
            }
        }

        // ---- online softmax (rows R0, R0+8) ----
        float m0 = -1e30f, m1 = -1e30f;
#pragma unroll
        for (int nt = 0; nt < 8; nt++) {
            m0 = fmaxf(m0, fmaxf(sacc[nt][0], sacc[nt][1]));
            m1 = fmaxf(m1, fmaxf(sacc[nt][2], sacc[nt][3]));
        }
        m0 = fmaxf(m0, __shfl_xor_sync(0xffffffffu, m0, 1));
        m0 = fmaxf(m0, __shfl_xor_sync(0xffffffffu, m0, 2));
        m1 = fmaxf(m1, __shfl_xor_sync(0xffffffffu, m1, 1));
        m1 = fmaxf(m1, __shfl_xor_sync(0xffffffffu, m1, 2));

        float nm0 = fmaxf(rmax0, m0), nm1 = fmaxf(rmax1, m1);
        float corr0 = __expf(rmax0 - nm0), corr1 = __expf(rmax1 - nm1);
        rmax0 = nm0; rmax1 = nm1;

        float ls0 = 0.0f, ls1 = 0.0f;
#pragma unroll
        for (int nt = 0; nt < 8; nt++) {
            float p0 = __expf(sacc[nt][0] - nm0);
            float p1 = __expf(sacc[nt][1] - nm0);
            float p2 = __expf(sacc[nt][2] - nm1);
            float p3 = __expf(sacc[nt][3] - nm1);
            ls0 += p0 + p1; ls1 += p2 + p3;
            // write P (warp-private rows) as tf32 A-operand
            uint32_t* d0 = &Ps[R0 * AQ_STR + nt * 8 + 2 * tg];
            d0[0] = f2tf32(p0); d0[1] = f2tf32(p1);
            uint32_t* d1 = &Ps[(R0 + 8) * AQ_STR + nt * 8 + 2 * tg];
            d1[0] = f2tf32(p2); d1[1] = f2tf32(p3);
        }
        ls0 += __shfl_xor_sync(0xffffffffu, ls0, 1);
        ls0 += __shfl_xor_sync(0xffffffffu, ls0, 2);
        ls1 += __shfl_xor_sync(0xffffffffu, ls1, 1);
        ls1 += __shfl_xor_sync(0xffffffffu, ls1, 2);
        rsum0 = rsum0 * corr0 + ls0;
        rsum1 = rsum1 * corr1 + ls1;

#pragma unroll
        for (int nt = 0; nt < 8; nt++) {
            O[nt][0] *= corr0; O[nt][1] *= corr0;
            O[nt][2] *= corr1; O[nt][3] *= corr1;
        }
        __syncwarp();

        // ---- O += P @ V : 8 k-steps (kcol), 8 n-frags (d) ----
#pragma unroll
        for (int kk = 0; kk < 8; kk++) {
            const int kb = kk * 8;
            uint32_t a0 = Ps[R0 * AQ_STR + kb + tg];
            uint32_t a1 = Ps[(R0 + 8) * AQ_STR + kb + tg];
            uint32_t a2 = Ps[R0 * AQ_STR + kb + tg + 4];
            uint32_t a3 = Ps[(R0 + 8) * AQ_STR + kb + tg + 4];
#pragma unroll
            for (int nt = 0; nt < 8; nt++) {
                uint32_t b0 = Vs[(kb + tg) * AK_STR + nt * 8 + gid];
                uint32_t b1 = Vs[(kb + tg + 4) * AK_STR + nt * 8 + gid];
                mma_tf32(O[nt][0], O[nt][1], O[nt][2], O[nt][3],
                         a0, a1, a2, a3, b0, b1);
            }
        }
    }

    // epilogue: normalize + store
    float inv0 = 1.0f / rsum0, inv1 = 1.0f / rsum1;
    float* obase = out + ((size_t)b * S_LEN + qi * 64) * 1024 + h * 64;
#pragma unroll
    for (int nt = 0; nt < 8; nt++) {
        int c = nt * 8 + 2 * tg;
        float2 v0, v1;
        v0.x = O[nt][0] * inv0; v0.y = O[nt][1] * inv0;
        v1.x = O[nt][2] * inv1; v1.y = O[nt][3] * inv1;
        *(float2*)(obase + (size_t)R0 * 1024 + c)       = v0;
        *(float2*)(obase + (size_t)(R0 + 8) * 1024 + c) = v1;
    }
}

// ---------------------------------------------------------------------------
// Launcher
// ---------------------------------------------------------------------------
extern "C" void kernel_launch(void* const* d_in, const int* in_sizes, int n_in,
                              void* d_out, int out_size)
{
    const float* x     = (const float*)d_in[0];
    // d_in[1] = mask: deterministic causal tril -> handled analytically
    const float* Wqkv  = (const float*)d_in[2];
    const float* Wproj = (const float*)d_in[3];
    const float* bproj = (const float*)d_in[4];
    const float* Aqkv  = (const float*)d_in[5];
    const float* Bqkv  = (const float*)d_in[6];
    const float* Aproj = (const float*)d_in[7];
    const float* Bproj = (const float*)d_in[8];

    float *wq, *wp, *qkv, *att;
    cudaGetSymbolAddress((void**)&wq,  g_Wqkv);
    cudaGetSymbolAddress((void**)&wp,  g_Wproj);
    cudaGetSymbolAddress((void**)&qkv, g_qkv);
    cudaGetSymbolAddress((void**)&att, g_att);

    cudaFuncSetAttribute(attn_mma,
                         cudaFuncAttributeMaxDynamicSharedMemorySize, ATTN2_SMEM_BYTES);

    // 1) fold LoRA into dense weights
    fuse_w<<<(N_QKV * E_DIM + 255) / 256, 256>>>(Wqkv, Aqkv, Bqkv, wq, N_QKV);
    fuse_w<<<(E_DIM * E_DIM + 255) / 256, 256>>>(Wproj, Aproj, Bproj, wp, E_DIM);

    // 2) qkv = x @ Wqkv_eff^T   (tf32 tensor cores)
    gemm_mma<false><<<dim3(N_QKV / 128, M_TOK / 128), 256>>>(
        x, wq, nullptr, qkv, E_DIM, N_QKV);

    // 3) causal flash attention (tf32 tensor cores)
    attn_mma<<<dim3(S_LEN / 64, B_NUM * H_NUM), 128, ATTN2_SMEM_BYTES>>>(qkv, att);

    // 4) out = att @ Wproj_eff^T + bproj   (tf32 tensor cores)
    gemm_mma<true><<<dim3(E_DIM / 128, M_TOK / 128), 256>>>(
        att, wp, bproj, (float*)d_out, E_DIM, E_DIM);
}

// round 6
// speedup vs baseline: 2.5747x; 1.2572x over previous
#include <cuda_runtime.h>
#include <cstdint>

// Problem constants
#define E_DIM   1024
#define H_NUM   16
#define B_NUM   4
#define S_LEN   2048
#define R_RANK  8
#define M_TOK   (B_NUM * S_LEN)      // 8192
#define N_QKV   (3 * E_DIM)          // 3072
#define LORA_SCALING 2.0f
#define ATTN_SCALE   0.125f          // D^-0.5

// ---------------------------------------------------------------------------
// Scratch (device globals: allocation-free per harness rules)
// ---------------------------------------------------------------------------
__device__ float g_Wqkv[N_QKV * E_DIM];          // fused QKV weight   (12 MB)
__device__ float g_Wproj[E_DIM * E_DIM];         // fused proj weight  (4 MB)
__device__ float g_qkv[(size_t)M_TOK * N_QKV];   // qkv activations (96 MB)
__device__ float g_att[(size_t)M_TOK * E_DIM];   // attention out   (32 MB)

// ---------------------------------------------------------------------------
// helpers
// ---------------------------------------------------------------------------
__device__ __forceinline__ uint32_t f2tf32(float f) {
    uint32_t o;
    asm("cvt.rna.tf32.f32 %0, %1;" : "=r"(o) : "f"(f));
    return o;
}
__device__ __forceinline__ void mma_tf32(float& c0, float& c1, float& c2, float& c3,
                                         uint32_t a0, uint32_t a1, uint32_t a2, uint32_t a3,
                                         uint32_t b0, uint32_t b1) {
    asm volatile(
        "mma.sync.aligned.m16n8k8.row.col.f32.tf32.tf32.f32 "
        "{%0,%1,%2,%3}, {%4,%5,%6,%7}, {%8,%9}, {%0,%1,%2,%3};"
        : "+f"(c0), "+f"(c1), "+f"(c2), "+f"(c3)
        : "r"(a0), "r"(a1), "r"(a2), "r"(a3), "r"(b0), "r"(b1));
}

// ---------------------------------------------------------------------------
// Kernel 1: fold LoRA into dense weight:  out = W + 2 * (Bm @ Am)
// ---------------------------------------------------------------------------
__global__ void fuse_w(const float* __restrict__ W, const float* __restrict__ Am,
                       const float* __restrict__ Bm, float* __restrict__ out,
                       int Nrows)
{
    int idx = blockIdx.x * 256 + threadIdx.x;
    if (idx >= Nrows * 1024) return;
    int n = idx >> 10;
    int k = idx & 1023;
    float acc = W[idx];
#pragma unroll
    for (int r = 0; r < R_RANK; r++)
        acc = fmaf(LORA_SCALING * Bm[n * R_RANK + r], Am[r * 1024 + k], acc);
    out[idx] = acc;
}

// ---------------------------------------------------------------------------
// tf32 tensor-core GEMM:  C[M,N] = A[M,K] @ W[N,K]^T (+ bias)  (unchanged)
// ---------------------------------------------------------------------------
template <bool BIAS>
__global__ __launch_bounds__(256)
void gemm_mma(const float* __restrict__ A, const float* __restrict__ W,
              const float* __restrict__ bias, float* __restrict__ C,
              int Kn, int Nn)
{
    __shared__ uint32_t As[2][128][20];
    __shared__ uint32_t Ws[2][128][20];

    const int t    = threadIdx.x;
    const int wid  = t >> 5;
    const int lid  = t & 31;
    const int gid  = lid >> 2;
    const int tg   = lid & 3;
    const int wm   = (wid >> 2) * 64;
    const int wn   = (wid & 3) * 32;
    const int row0 = blockIdx.y << 7;
    const int col0 = blockIdx.x << 7;

    const int lr = t >> 2;
    const int lk = (t & 3) << 2;
    const float* Ap0 = A + (size_t)(row0 + lr) * Kn + lk;
    const float* Ap1 = Ap0 + (size_t)64 * Kn;
    const float* Wp0 = W + (size_t)(col0 + lr) * Kn + lk;
    const float* Wp1 = Wp0 + (size_t)64 * Kn;

    float acc[4][4][4];
#pragma unroll
    for (int i = 0; i < 4; i++)
#pragma unroll
        for (int j = 0; j < 4; j++)
#pragma unroll
            for (int r = 0; r < 4; r++) acc[i][j][r] = 0.0f;

    const int nkt = Kn >> 4;

    {
        float4 a0 = *(const float4*)(Ap0);
        float4 a1 = *(const float4*)(Ap1);
        float4 w0 = *(const float4*)(Wp0);
        float4 w1 = *(const float4*)(Wp1);
        As[0][lr][lk+0] = f2tf32(a0.x); As[0][lr][lk+1] = f2tf32(a0.y);
        As[0][lr][lk+2] = f2tf32(a0.z); As[0][lr][lk+3] = f2tf32(a0.w);
        As[0][lr+64][lk+0] = f2tf32(a1.x); As[0][lr+64][lk+1] = f2tf32(a1.y);
        As[0][lr+64][lk+2] = f2tf32(a1.z); As[0][lr+64][lk+3] = f2tf32(a1.w);
        Ws[0][lr][lk+0] = f2tf32(w0.x); Ws[0][lr][lk+1] = f2tf32(w0.y);
        Ws[0][lr][lk+2] = f2tf32(w0.z); Ws[0][lr][lk+3] = f2tf32(w0.w);
        Ws[0][lr+64][lk+0] = f2tf32(w1.x); Ws[0][lr+64][lk+1] = f2tf32(w1.y);
        Ws[0][lr+64][lk+2] = f2tf32(w1.z); Ws[0][lr+64][lk+3] = f2tf32(w1.w);
    }
    __syncthreads();

    for (int kt = 0; kt < nkt; kt++) {
        const int cur = kt & 1, nxt = cur ^ 1;

        float4 pa0, pa1, pw0, pw1;
        if (kt + 1 < nkt) {
            const int k0 = (kt + 1) << 4;
            pa0 = *(const float4*)(Ap0 + k0);
            pa1 = *(const float4*)(Ap1 + k0);
            pw0 = *(const float4*)(Wp0 + k0);
            pw1 = *(const float4*)(Wp1 + k0);
        }

#pragma unroll
        for (int kc = 0; kc < 16; kc += 8) {
            uint32_t af[4][4], bf[4][2];
#pragma unroll
            for (int mt = 0; mt < 4; mt++) {
                const int r = wm + mt * 16 + gid;
                af[mt][0] = As[cur][r][kc + tg];
                af[mt][1] = As[cur][r + 8][kc + tg];
                af[mt][2] = As[cur][r][kc + tg + 4];
                af[mt][3] = As[cur][r + 8][kc + tg + 4];
            }
#pragma unroll
            for (int nt = 0; nt < 4; nt++) {
                const int n = wn + nt * 8 + gid;
                bf[nt][0] = Ws[cur][n][kc + tg];
                bf[nt][1] = Ws[cur][n][kc + tg + 4];
            }
#pragma unroll
            for (int mt = 0; mt < 4; mt++)
#pragma unroll
                for (int nt = 0; nt < 4; nt++)
                    mma_tf32(acc[mt][nt][0], acc[mt][nt][1],
                             acc[mt][nt][2], acc[mt][nt][3],
                             af[mt][0], af[mt][1], af[mt][2], af[mt][3],
                             bf[nt][0], bf[nt][1]);
        }

        if (kt + 1 < nkt) {
            As[nxt][lr][lk+0] = f2tf32(pa0.x); As[nxt][lr][lk+1] = f2tf32(pa0.y);
            As[nxt][lr][lk+2] = f2tf32(pa0.z); As[nxt][lr][lk+3] = f2tf32(pa0.w);
            As[nxt][lr+64][lk+0] = f2tf32(pa1.x); As[nxt][lr+64][lk+1] = f2tf32(pa1.y);
            As[nxt][lr+64][lk+2] = f2tf32(pa1.z); As[nxt][lr+64][lk+3] = f2tf32(pa1.w);
            Ws[nxt][lr][lk+0] = f2tf32(pw0.x); Ws[nxt][lr][lk+1] = f2tf32(pw0.y);
            Ws[nxt][lr][lk+2] = f2tf32(pw0.z); Ws[nxt][lr][lk+3] = f2tf32(pw0.w);
            Ws[nxt][lr+64][lk+0] = f2tf32(pw1.x); Ws[nxt][lr+64][lk+1] = f2tf32(pw1.y);
            Ws[nxt][lr+64][lk+2] = f2tf32(pw1.z); Ws[nxt][lr+64][lk+3] = f2tf32(pw1.w);
        }
        __syncthreads();
    }

#pragma unroll
    for (int mt = 0; mt < 4; mt++) {
        const int r = row0 + wm + mt * 16 + gid;
#pragma unroll
        for (int nt = 0; nt < 4; nt++) {
            const int c = col0 + wn + nt * 8 + tg * 2;
            float2 v0, v1;
            v0.x = acc[mt][nt][0]; v0.y = acc[mt][nt][1];
            v1.x = acc[mt][nt][2]; v1.y = acc[mt][nt][3];
            if (BIAS) {
                float b0 = bias[c], b1 = bias[c + 1];
                v0.x += b0; v0.y += b1;
                v1.x += b0; v1.y += b1;
            }
            *(float2*)(&C[(size_t)r * Nn + c])       = v0;
            *(float2*)(&C[(size_t)(r + 8) * Nn + c]) = v1;
        }
    }
}

// ---------------------------------------------------------------------------
// Kernel 3: causal flash attention on tensor cores (tf32 mma, fp32 softmax)
//   128 threads (4 warps); q-tile 128 rows; warp w owns q-rows [32w, 32w+32)
//   Qs[128][68] (q,d) scale folded | Ps[128][68] (q,k)
//   Ks[64][68]  (k,d) NATURAL layout | Vs[64][68] (k,d)
// ---------------------------------------------------------------------------
#define QP_STR 68
#define KV_STR 68
#define ATTN2_SMEM_BYTES ((128*QP_STR*2 + 64*KV_STR*2) * 4)   // 104448

__global__ __launch_bounds__(128)
void attn_mma(const float* __restrict__ qkv, float* __restrict__ out)
{
    extern __shared__ uint32_t smu[];
    uint32_t* Qs = smu;                      // [128][QP_STR]
    uint32_t* Ps = Qs + 128 * QP_STR;        // [128][QP_STR]
    uint32_t* Ks = Ps + 128 * QP_STR;        // [64][KV_STR]
    uint32_t* Vs = Ks + 64 * KV_STR;         // [64][KV_STR]

    const int t   = threadIdx.x;
    const int w   = t >> 5;                  // 0..3
    const int lid = t & 31;
    const int gid = lid >> 2;
    const int tg  = lid & 3;

    const int qi = (int)gridDim.x - 1 - (int)blockIdx.x;  // long blocks first
    const int bh = blockIdx.y;
    const int b  = bh >> 4;
    const int h  = bh & 15;

    const float* qbase = qkv + (size_t)b * S_LEN * 3072 + h * 64;
    const float* kbase = qbase + 1024;
    const float* vbase = qbase + 2048;

    const int lr = t >> 4;            // 0..7
    const int dd = (t & 15) * 4;      // 0..60

    // load Q tile (128 rows, scale folded), packed uint4 stores
    {
        const float* qp = qbase + (size_t)(qi * 128 + lr) * 3072 + dd;
#pragma unroll
        for (int p = 0; p < 16; p++) {
            int r = lr + p * 8;
            float4 q4 = *(const float4*)(qp + (size_t)(p * 8) * 3072);
            uint4 u;
            u.x = f2tf32(q4.x * ATTN_SCALE); u.y = f2tf32(q4.y * ATTN_SCALE);
            u.z = f2tf32(q4.z * ATTN_SCALE); u.w = f2tf32(q4.w * ATTN_SCALE);
            *(uint4*)&Qs[r * QP_STR + dd] = u;
        }
    }

    const int R0 = w * 32 + gid;      // warp rows: R0, R0+8, R0+16, R0+24
    float O[2][8][4];
    float rmax[2][2], rsum[2][2];
#pragma unroll
    for (int mt = 0; mt < 2; mt++) {
        rmax[mt][0] = -1e30f; rmax[mt][1] = -1e30f;
        rsum[mt][0] = 0.0f;   rsum[mt][1] = 0.0f;
#pragma unroll
        for (int nt = 0; nt < 8; nt++)
#pragma unroll
            for (int r = 0; r < 4; r++) O[mt][nt][r] = 0.0f;
    }

    const int jmax = 2 * qi + 1;
    for (int j = 0; j <= jmax; j++) {
        __syncthreads();   // prior compute done reading Ks/Vs (covers Q on j=0)

        // load K and V tile j (natural [k][d] layout, packed stores)
        const float* kp = kbase + (size_t)(j * 64 + lr) * 3072 + dd;
        const float* vp = vbase + (size_t)(j * 64 + lr) * 3072 + dd;
#pragma unroll
        for (int p = 0; p < 8; p++) {
            int r = lr + p * 8;
            float4 k4 = *(const float4*)(kp + (size_t)(p * 8) * 3072);
            uint4 uk;
            uk.x = f2tf32(k4.x); uk.y = f2tf32(k4.y);
            uk.z = f2tf32(k4.z); uk.w = f2tf32(k4.w);
            *(uint4*)&Ks[r * KV_STR + dd] = uk;
            float4 v4 = *(const float4*)(vp + (size_t)(p * 8) * 3072);
            uint4 uv;
            uv.x = f2tf32(v4.x); uv.y = f2tf32(v4.y);
            uv.z = f2tf32(v4.z); uv.w = f2tf32(v4.w);
            *(uint4*)&Vs[r * KV_STR + dd] = uv;
        }
        __syncthreads();

        // warp fully masked? (all cols > all rows)
        if (j * 64 > qi * 128 + w * 32 + 31) continue;

        // ---- S = Q @ K^T ----
        float sacc[2][8][4];
#pragma unroll
        for (int mt = 0; mt < 2; mt++)
#pragma unroll
            for (int nt = 0; nt < 8; nt++)
#pragma unroll
                for (int r = 0; r < 4; r++) sacc[mt][nt][r] = 0.0f;

#pragma unroll
        for (int kk = 0; kk < 8; kk++) {
            const int kb = kk * 8;
            uint32_t a[2][4];
#pragma unroll
            for (int mt = 0; mt < 2; mt++) {
                const int rr = R0 + mt * 16;
                a[mt][0] = Qs[rr * QP_STR + kb + tg];
                a[mt][1] = Qs[(rr + 8) * QP_STR + kb + tg];
                a[mt][2] = Qs[rr * QP_STR + kb + tg + 4];
                a[mt][3] = Qs[(rr + 8) * QP_STR + kb + tg + 4];
            }
#pragma unroll
            for (int nt = 0; nt < 8; nt++) {
                uint32_t b0 = Ks[(nt * 8 + gid) * KV_STR + kb + tg];
                uint32_t b1 = Ks[(nt * 8 + gid) * KV_STR + kb + tg + 4];
                mma_tf32(sacc[0][nt][0], sacc[0][nt][1], sacc[0][nt][2], sacc[0][nt][3],
                         a[0][0], a[0][1], a[0][2], a[0][3], b0, b1);
                mma_tf32(sacc[1][nt][0], sacc[1][nt][1], sacc[1][nt][2], sacc[1][nt][3],
                         a[1][0], a[1][1], a[1][2], a[1][3], b0, b1);
            }
        }

        // causal mask (only when tile straddles this warp's diagonal range)
        if (j * 64 + 63 > qi * 128 + w * 32) {
#pragma unroll
            for (int mt = 0; mt < 2; mt++) {
                const int rg0 = qi * 128 + R0 + mt * 16;
                const int rg1 = rg0 + 8;
#pragma unroll
                for (int nt = 0; nt < 8; nt++) {
                    const int cg = j * 64 + nt * 8 + 2 * tg;
                    if (cg     > rg0) sacc[mt][nt][0] = -1e30f;
                    if (cg + 1 > rg0) sacc[mt][nt][1] = -1e30f;
                    if (cg     > rg1) sacc[mt][nt][2] = -1e30f;
                    if (cg + 1 > rg1) sacc[mt][nt][3] = -1e30f;
                }
            }
        }

        // ---- online softmax (4 rows per thread) ----
#pragma unroll
        for (int mt = 0; mt < 2; mt++)
#pragma unroll
            for (int hf = 0; hf < 2; hf++) {
                const int i0 = hf * 2, i1 = hf * 2 + 1;
                float m = -1e30f;
#pragma unroll
                for (int nt = 0; nt < 8; nt++)
                    m = fmaxf(m, fmaxf(sacc[mt][nt][i0], sacc[mt][nt][i1]));
                m = fmaxf(m, __shfl_xor_sync(0xffffffffu, m, 1));
                m = fmaxf(m, __shfl_xor_sync(0xffffffffu, m, 2));

                float nm = fmaxf(rmax[mt][hf], m);
                float corr = __expf(rmax[mt][hf] - nm);
                rmax[mt][hf] = nm;

                const int prow = R0 + mt * 16 + hf * 8;
                float ls = 0.0f;
#pragma unroll
                for (int nt = 0; nt < 8; nt++) {
                    float p0 = __expf(sacc[mt][nt][i0] - nm);
                    float p1 = __expf(sacc[mt][nt][i1] - nm);
                    ls += p0 + p1;
                    uint32_t* d = &Ps[prow * QP_STR + nt * 8 + 2 * tg];
                    d[0] = f2tf32(p0); d[1] = f2tf32(p1);
                }
                ls += __shfl_xor_sync(0xffffffffu, ls, 1);
                ls += __shfl_xor_sync(0xffffffffu, ls, 2);
                rsum[mt][hf] = rsum[mt][hf] * corr + ls;

#pragma unroll
                for (int nt = 0; nt < 8; nt++) {
                    O[mt][nt][i0] *= corr;
                    O[mt][nt][i1] *= corr;
                }
            }
        __syncwarp();

        // ---- O += P @ V ----
#pragma unroll
        for (int kk = 0; kk < 8; kk++) {
            const int kb = kk * 8;
            uint32_t a[2][4];
#pragma unroll
            for (int mt = 0; mt < 2; mt++) {
                const int rr = R0 + mt * 16;
                a[mt][0] = Ps[rr * QP_STR + kb + tg];
                a[mt][1] = Ps[(rr + 8) * QP_STR + kb + tg];
                a[mt][2] = Ps[rr * QP_STR + kb + tg + 4];
                a[mt][3] = Ps[(rr + 8) * QP_STR + kb + tg + 4];
            }
#pragma unroll
            for (int nt = 0; nt < 8; nt++) {
                uint32_t b0 = Vs[(kb + tg) * KV_STR + nt * 8 + gid];
                uint32_t b1 = Vs[(kb + tg + 4) * KV_STR + nt * 8 + gid];
                mma_tf32(O[0][nt][0], O[0][nt][1], O[0][nt][2], O[0][nt][3],
                         a[0][0], a[0][1], a[0][2], a[0][3], b0, b1);
                mma_tf32(O[1][nt][0], O[1][nt][1], O[1][nt][2], O[1][nt][3],
                         a[1][0], a[1][1], a[1][2], a[1][3], b0, b1);
            }
        }
    }

    // epilogue: normalize + store
    float* obase = out + ((size_t)b * S_LEN + qi * 128) * 1024 + h * 64;
#pragma unroll
    for (int mt = 0; mt < 2; mt++) {
        const float inv0 = 1.0f / rsum[mt][0];
        const float inv1 = 1.0f / rsum[mt][1];
        const int r = R0 + mt * 16;
#pragma unroll
        for (int nt = 0; nt < 8; nt++) {
            const int c = nt * 8 + 2 * tg;
            float2 v0, v1;
            v0.x = O[mt][nt][0] * inv0; v0.y = O[mt][nt][1] * inv0;
            v1.x = O[mt][nt][2] * inv1; v1.y = O[mt][nt][3] * inv1;
            *(float2*)(obase + (size_t)r * 1024 + c)       = v0;
            *(float2*)(obase + (size_t)(r + 8) * 1024 + c) = v1;
        }
    }
}

// ---------------------------------------------------------------------------
// Launcher
// ---------------------------------------------------------------------------
extern "C" void kernel_launch(void* const* d_in, const int* in_sizes, int n_in,
                              void* d_out, int out_size)
{
    const float* x     = (const float*)d_in[0];
    // d_in[1] = mask: deterministic causal tril -> handled analytically
    const float* Wqkv  = (const float*)d_in[2];
    const float* Wproj = (const float*)d_in[3];
    const float* bproj = (const float*)d_in[4];
    const float* Aqkv  = (const float*)d_in[5];
    const float* Bqkv  = (const float*)d_in[6];
    const float* Aproj = (const float*)d_in[7];
    const float* Bproj = (const float*)d_in[8];

    float *wq, *wp, *qkv, *att;
    cudaGetSymbolAddress((void**)&wq,  g_Wqkv);
    cudaGetSymbolAddress((void**)&wp,  g_Wproj);
    cudaGetSymbolAddress((void**)&qkv, g_qkv);
    cudaGetSymbolAddress((void**)&att, g_att);

    cudaFuncSetAttribute(attn_mma,
                         cudaFuncAttributeMaxDynamicSharedMemorySize, ATTN2_SMEM_BYTES);

    // 1) fold LoRA into dense weights
    fuse_w<<<(N_QKV * E_DIM + 255) / 256, 256>>>(Wqkv, Aqkv, Bqkv, wq, N_QKV);
    fuse_w<<<(E_DIM * E_DIM + 255) / 256, 256>>>(Wproj, Aproj, Bproj, wp, E_DIM);

    // 2) qkv = x @ Wqkv_eff^T   (tf32 tensor cores)
    gemm_mma<false><<<dim3(N_QKV / 128, M_TOK / 128), 256>>>(
        x, wq, nullptr, qkv, E_DIM, N_QKV);

    // 3) causal flash attention (tf32 tensor cores, 128-row q-tiles)
    attn_mma<<<dim3(S_LEN / 128, B_NUM * H_NUM), 128, ATTN2_SMEM_BYTES>>>(qkv, att);

    // 4) out = att @ Wproj_eff^T + bproj   (tf32 tensor cores)
    gemm_mma<true><<<dim3(E_DIM / 128, M_TOK / 128), 256>>>(
        att, wp, bproj, (float*)d_out, E_DIM, E_DIM);
}

// round 7
// speedup vs baseline: 2.8976x; 1.1254x over previous
#include <cuda_runtime.h>
#include <cstdint>

// Problem constants
#define E_DIM   1024
#define H_NUM   16
#define B_NUM   4
#define S_LEN   2048
#define R_RANK  8
#define M_TOK   (B_NUM * S_LEN)      // 8192
#define N_QKV   (3 * E_DIM)          // 3072
#define LORA_SCALING 2.0f
#define ATTN_SCALE   0.125f          // D^-0.5

// ---------------------------------------------------------------------------
// Scratch (device globals: allocation-free per harness rules)
// ---------------------------------------------------------------------------
__device__ float g_Wqkv[N_QKV * E_DIM];          // fused QKV weight   (12 MB)
__device__ float g_Wproj[E_DIM * E_DIM];         // fused proj weight  (4 MB)
__device__ float g_qkv[(size_t)M_TOK * N_QKV];   // qkv activations (96 MB)
__device__ float g_att[(size_t)M_TOK * E_DIM];   // attention out   (32 MB)

// ---------------------------------------------------------------------------
// helpers
// ---------------------------------------------------------------------------
__device__ __forceinline__ uint32_t f2tf32(float f) {
    uint32_t o;
    asm("cvt.rna.tf32.f32 %0, %1;" : "=r"(o) : "f"(f));
    return o;
}
__device__ __forceinline__ void mma_tf32(float& c0, float& c1, float& c2, float& c3,
                                         uint32_t a0, uint32_t a1, uint32_t a2, uint32_t a3,
                                         uint32_t b0, uint32_t b1) {
    asm volatile(
        "mma.sync.aligned.m16n8k8.row.col.f32.tf32.tf32.f32 "
        "{%0,%1,%2,%3}, {%4,%5,%6,%7}, {%8,%9}, {%0,%1,%2,%3};"
        : "+f"(c0), "+f"(c1), "+f"(c2), "+f"(c3)
        : "r"(a0), "r"(a1), "r"(a2), "r"(a3), "r"(b0), "r"(b1));
}
__device__ __forceinline__ void ldsm_x4(uint32_t& r0, uint32_t& r1,
                                        uint32_t& r2, uint32_t& r3, uint32_t addr) {
    asm volatile("ldmatrix.sync.aligned.m8n8.x4.shared.b16 {%0,%1,%2,%3}, [%4];"
                 : "=r"(r0), "=r"(r1), "=r"(r2), "=r"(r3) : "r"(addr));
}

// ---------------------------------------------------------------------------
// Kernel 1: fold LoRA into dense weight:  out = W + 2 * (Bm @ Am)
// ---------------------------------------------------------------------------
__global__ void fuse_w(const float* __restrict__ W, const float* __restrict__ Am,
                       const float* __restrict__ Bm, float* __restrict__ out,
                       int Nrows)
{
    int idx = blockIdx.x * 256 + threadIdx.x;
    if (idx >= Nrows * 1024) return;
    int n = idx >> 10;
    int k = idx & 1023;
    float acc = W[idx];
#pragma unroll
    for (int r = 0; r < R_RANK; r++)
        acc = fmaf(LORA_SCALING * Bm[n * R_RANK + r], Am[r * 1024 + k], acc);
    out[idx] = acc;
}

// ---------------------------------------------------------------------------
// tf32 tensor-core GEMM:  C[M,N] = A[M,K] @ W[N,K]^T (+ bias)
//   tile 128x128, BK=16, 256 threads (8 warps: 2x4, 64x32 per warp)
//   fragment loads via ldmatrix.x4
// ---------------------------------------------------------------------------
template <bool BIAS>
__global__ __launch_bounds__(256)
void gemm_mma(const float* __restrict__ A, const float* __restrict__ W,
              const float* __restrict__ bias, float* __restrict__ C,
              int Kn, int Nn)
{
    __shared__ uint32_t As[2][128][20];
    __shared__ uint32_t Ws[2][128][20];

    const int t    = threadIdx.x;
    const int wid  = t >> 5;
    const int lid  = t & 31;
    const int gid  = lid >> 2;
    const int tg   = lid & 3;
    const int wm   = (wid >> 2) * 64;
    const int wn   = (wid & 3) * 32;
    const int row0 = blockIdx.y << 7;
    const int col0 = blockIdx.x << 7;

    // ldmatrix lane addressing
    const int mh = lid >> 3;          // matrix id 0..3
    const int rr = lid & 7;
    const uint32_t As_sh = (uint32_t)__cvta_generic_to_shared(&As[0][0][0]);
    const uint32_t Ws_sh = (uint32_t)__cvta_generic_to_shared(&Ws[0][0][0]);
    const uint32_t a_lane = ((((mh & 1) * 8 + rr) * 20 + (mh >> 1) * 4) << 2);
    const uint32_t b_lane = ((((mh >> 1) * 8 + rr) * 20 + (mh & 1) * 4) << 2);

    const int lr = t >> 2;
    const int lk = (t & 3) << 2;
    const float* Ap0 = A + (size_t)(row0 + lr) * Kn + lk;
    const float* Ap1 = Ap0 + (size_t)64 * Kn;
    const float* Wp0 = W + (size_t)(col0 + lr) * Kn + lk;
    const float* Wp1 = Wp0 + (size_t)64 * Kn;

    float acc[4][4][4];
#pragma unroll
    for (int i = 0; i < 4; i++)
#pragma unroll
        for (int j = 0; j < 4; j++)
#pragma unroll
            for (int r = 0; r < 4; r++) acc[i][j][r] = 0.0f;

    const int nkt = Kn >> 4;

    {
        float4 a0 = *(const float4*)(Ap0);
        float4 a1 = *(const float4*)(Ap1);
        float4 w0 = *(const float4*)(Wp0);
        float4 w1 = *(const float4*)(Wp1);
        As[0][lr][lk+0] = f2tf32(a0.x); As[0][lr][lk+1] = f2tf32(a0.y);
        As[0][lr][lk+2] = f2tf32(a0.z); As[0][lr][lk+3] = f2tf32(a0.w);
        As[0][lr+64][lk+0] = f2tf32(a1.x); As[0][lr+64][lk+1] = f2tf32(a1.y);
        As[0][lr+64][lk+2] = f2tf32(a1.z); As[0][lr+64][lk+3] = f2tf32(a1.w);
        Ws[0][lr][lk+0] = f2tf32(w0.x); Ws[0][lr][lk+1] = f2tf32(w0.y);
        Ws[0][lr][lk+2] = f2tf32(w0.z); Ws[0][lr][lk+3] = f2tf32(w0.w);
        Ws[0][lr+64][lk+0] = f2tf32(w1.x); Ws[0][lr+64][lk+1] = f2tf32(w1.y);
        Ws[0][lr+64][lk+2] = f2tf32(w1.z); Ws[0][lr+64][lk+3] = f2tf32(w1.w);
    }
    __syncthreads();

    for (int kt = 0; kt < nkt; kt++) {
        const int cur = kt & 1, nxt = cur ^ 1;

        float4 pa0, pa1, pw0, pw1;
        if (kt + 1 < nkt) {
            const int k0 = (kt + 1) << 4;
            pa0 = *(const float4*)(Ap0 + k0);
            pa1 = *(const float4*)(Ap1 + k0);
            pw0 = *(const float4*)(Wp0 + k0);
            pw1 = *(const float4*)(Wp1 + k0);
        }

#pragma unroll
        for (int kc = 0; kc < 16; kc += 8) {
            uint32_t af[4][4], bf[4][2];
#pragma unroll
            for (int mt = 0; mt < 4; mt++)
                ldsm_x4(af[mt][0], af[mt][1], af[mt][2], af[mt][3],
                        As_sh + ((((cur * 128 + wm + mt * 16) * 20) + kc) << 2) + a_lane);
#pragma unroll
            for (int p = 0; p < 2; p++)
                ldsm_x4(bf[2*p][0], bf[2*p][1], bf[2*p+1][0], bf[2*p+1][1],
                        Ws_sh + ((((cur * 128 + wn + p * 16) * 20) + kc) << 2) + b_lane);
#pragma unroll
            for (int mt = 0; mt < 4; mt++)
#pragma unroll
                for (int nt = 0; nt < 4; nt++)
                    mma_tf32(acc[mt][nt][0], acc[mt][nt][1],
                             acc[mt][nt][2], acc[mt][nt][3],
                             af[mt][0], af[mt][1], af[mt][2], af[mt][3],
                             bf[nt][0], bf[nt][1]);
        }

        if (kt + 1 < nkt) {
            As[nxt][lr][lk+0] = f2tf32(pa0.x); As[nxt][lr][lk+1] = f2tf32(pa0.y);
            As[nxt][lr][lk+2] = f2tf32(pa0.z); As[nxt][lr][lk+3] = f2tf32(pa0.w);
            As[nxt][lr+64][lk+0] = f2tf32(pa1.x); As[nxt][lr+64][lk+1] = f2tf32(pa1.y);
            As[nxt][lr+64][lk+2] = f2tf32(pa1.z); As[nxt][lr+64][lk+3] = f2tf32(pa1.w);
            Ws[nxt][lr][lk+0] = f2tf32(pw0.x); Ws[nxt][lr][lk+1] = f2tf32(pw0.y);
            Ws[nxt][lr][lk+2] = f2tf32(pw0.z); Ws[nxt][lr][lk+3] = f2tf32(pw0.w);
            Ws[nxt][lr+64][lk+0] = f2tf32(pw1.x); Ws[nxt][lr+64][lk+1] = f2tf32(pw1.y);
            Ws[nxt][lr+64][lk+2] = f2tf32(pw1.z); Ws[nxt][lr+64][lk+3] = f2tf32(pw1.w);
        }
        __syncthreads();
    }

#pragma unroll
    for (int mt = 0; mt < 4; mt++) {
        const int r = row0 + wm + mt * 16 + gid;
#pragma unroll
        for (int nt = 0; nt < 4; nt++) {
            const int c = col0 + wn + nt * 8 + tg * 2;
            float2 v0, v1;
            v0.x = acc[mt][nt][0]; v0.y = acc[mt][nt][1];
            v1.x = acc[mt][nt][2]; v1.y = acc[mt][nt][3];
            if (BIAS) {
                float b0 = bias[c], b1 = bias[c + 1];
                v0.x += b0; v0.y += b1;
                v1.x += b0; v1.y += b1;
            }
            *(float2*)(&C[(size_t)r * Nn + c])       = v0;
            *(float2*)(&C[(size_t)(r + 8) * Nn + c]) = v1;
        }
    }
}

// ---------------------------------------------------------------------------
// Kernel 3: causal flash attention on tensor cores (tf32 mma, fp32 softmax)
//   128 threads (4 warps); q-tile 128 rows; warp w owns q-rows [32w, 32w+32)
//   Q/K/P fragments via ldmatrix.x4; V fragments scalar (natural layout)
// ---------------------------------------------------------------------------
#define QP_STR 68
#define KV_STR 68
#define ATTN2_SMEM_BYTES ((128*QP_STR*2 + 64*KV_STR*2) * 4)   // 104448

__global__ __launch_bounds__(128)
void attn_mma(const float* __restrict__ qkv, float* __restrict__ out)
{
    extern __shared__ uint32_t smu[];
    uint32_t* Qs = smu;                      // [128][QP_STR]
    uint32_t* Ps = Qs + 128 * QP_STR;        // [128][QP_STR]
    uint32_t* Ks = Ps + 128 * QP_STR;        // [64][KV_STR]
    uint32_t* Vs = Ks + 64 * KV_STR;         // [64][KV_STR]

    const int t   = threadIdx.x;
    const int w   = t >> 5;                  // 0..3
    const int lid = t & 31;
    const int gid = lid >> 2;
    const int tg  = lid & 3;

    // ldmatrix lane addressing
    const int mh = lid >> 3;
    const int rr = lid & 7;
    const uint32_t Qs_sh = (uint32_t)__cvta_generic_to_shared(Qs);
    const uint32_t Ps_sh = (uint32_t)__cvta_generic_to_shared(Ps);
    const uint32_t Ks_sh = (uint32_t)__cvta_generic_to_shared(Ks);
    const uint32_t qp_lane = ((((mh & 1) * 8 + rr) * QP_STR + (mh >> 1) * 4) << 2);
    const uint32_t kb_lane = ((((mh >> 1) * 8 + rr) * KV_STR + (mh & 1) * 4) << 2);

    const int qi = (int)gridDim.x - 1 - (int)blockIdx.x;  // long blocks first
    const int bh = blockIdx.y;
    const int b  = bh >> 4;
    const int h  = bh & 15;

    const float* qbase = qkv + (size_t)b * S_LEN * 3072 + h * 64;
    const float* kbase = qbase + 1024;
    const float* vbase = qbase + 2048;

    const int lr = t >> 4;            // 0..7
    const int dd = (t & 15) * 4;      // 0..60

    // load Q tile (128 rows, scale folded), packed uint4 stores
    {
        const float* qp = qbase + (size_t)(qi * 128 + lr) * 3072 + dd;
#pragma unroll
        for (int p = 0; p < 16; p++) {
            int r = lr + p * 8;
            float4 q4 = *(const float4*)(qp + (size_t)(p * 8) * 3072);
            uint4 u;
            u.x = f2tf32(q4.x * ATTN_SCALE); u.y = f2tf32(q4.y * ATTN_SCALE);
            u.z = f2tf32(q4.z * ATTN_SCALE); u.w = f2tf32(q4.w * ATTN_SCALE);
            *(uint4*)&Qs[r * QP_STR + dd] = u;
        }
    }

    const int R0 = w * 32 + gid;      // warp rows: R0, R0+8, R0+16, R0+24
    float O[2][8][4];
    float rmax[2][2], rsum[2][2];
#pragma unroll
    for (int mt = 0; mt < 2; mt++) {
        rmax[mt][0] = -1e30f; rmax[mt][1] = -1e30f;
        rsum[mt][0] = 0.0f;   rsum[mt][1] = 0.0f;
#pragma unroll
        for (int nt = 0; nt < 8; nt++)
#pragma unroll
            for (int r = 0; r < 4; r++) O[mt][nt][r] = 0.0f;
    }

    const int jmax = 2 * qi + 1;
    for (int j = 0; j <= jmax; j++) {
        __syncthreads();   // prior compute done reading Ks/Vs (covers Q on j=0)

        // load K and V tile j (natural [k][d] layout, packed stores)
        const float* kp = kbase + (size_t)(j * 64 + lr) * 3072 + dd;
        const float* vp = vbase + (size_t)(j * 64 + lr) * 3072 + dd;
#pragma unroll
        for (int p = 0; p < 8; p++) {
            int r = lr + p * 8;
            float4 k4 = *(const float4*)(kp + (size_t)(p * 8) * 3072);
            uint4 uk;
            uk.x = f2tf32(k4.x); uk.y = f2tf32(k4.y);
            uk.z = f2tf32(k4.z); uk.w = f2tf32(k4.w);
            *(uint4*)&Ks[r * KV_STR + dd] = uk;
            float4 v4 = *(const float4*)(vp + (size_t)(p * 8) * 3072);
            uint4 uv;
            uv.x = f2tf32(v4.x); uv.y = f2tf32(v4.y);
            uv.z = f2tf32(v4.z); uv.w = f2tf32(v4.w);
            *(uint4*)&Vs[r * KV_STR + dd] = uv;
        }
        __syncthreads();

        // warp fully masked? (all cols > all rows)
        if (j * 64 > qi * 128 + w * 32 + 31) continue;

        // ---- S = Q @ K^T ----
        float sacc[2][8][4];
#pragma unroll
        for (int mt = 0; mt < 2; mt++)
#pragma unroll
            for (int nt = 0; nt < 8; nt++)
#pragma unroll
                for (int r = 0; r < 4; r++) sacc[mt][nt][r] = 0.0f;

#pragma unroll
        for (int kk = 0; kk < 8; kk++) {
            const int kb = kk * 8;
            uint32_t a[2][4], bk[8][2];
#pragma unroll
            for (int mt = 0; mt < 2; mt++)
                ldsm_x4(a[mt][0], a[mt][1], a[mt][2], a[mt][3],
                        Qs_sh + ((((w * 32 + mt * 16) * QP_STR) + kb) << 2) + qp_lane);
#pragma unroll
            for (int p = 0; p < 4; p++)
                ldsm_x4(bk[2*p][0], bk[2*p][1], bk[2*p+1][0], bk[2*p+1][1],
                        Ks_sh + ((((p * 16) * KV_STR) + kb) << 2) + kb_lane);
#pragma unroll
            for (int nt = 0; nt < 8; nt++) {
                mma_tf32(sacc[0][nt][0], sacc[0][nt][1], sacc[0][nt][2], sacc[0][nt][3],
                         a[0][0], a[0][1], a[0][2], a[0][3], bk[nt][0], bk[nt][1]);
                mma_tf32(sacc[1][nt][0], sacc[1][nt][1], sacc[1][nt][2], sacc[1][nt][3],
                         a[1][0], a[1][1], a[1][2], a[1][3], bk[nt][0], bk[nt][1]);
            }
        }

        // causal mask (only when tile straddles this warp's diagonal range)
        if (j * 64 + 63 > qi * 128 + w * 32) {
#pragma unroll
            for (int mt = 0; mt < 2; mt++) {
                const int rg0 = qi * 128 + R0 + mt * 16;
                const int rg1 = rg0 + 8;
#pragma unroll
                for (int nt = 0; nt < 8; nt++) {
                    const int cg = j * 64 + nt * 8 + 2 * tg;
                    if (cg     > rg0) sacc[mt][nt][0] = -1e30f;
                    if (cg + 1 > rg0) sacc[mt][nt][1] = -1e30f;
                    if (cg     > rg1) sacc[mt][nt][2] = -1e30f;
                    if (cg + 1 > rg1) sacc[mt][nt][3] = -1e30f;
                }
            }
        }

        // ---- online softmax (4 rows per thread) ----
#pragma unroll
        for (int mt = 0; mt < 2; mt++)
#pragma unroll
            for (int hf = 0; hf < 2; hf++) {
                const int i0 = hf * 2, i1 = hf * 2 + 1;
                float m = -1e30f;
#pragma unroll
                for (int nt = 0; nt < 8; nt++)
                    m = fmaxf(m, fmaxf(sacc[mt][nt][i0], sacc[mt][nt][i1]));
                m = fmaxf(m, __shfl_xor_sync(0xffffffffu, m, 1));
                m = fmaxf(m, __shfl_xor_sync(0xffffffffu, m, 2));

                float nm = fmaxf(rmax[mt][hf], m);
                float corr = __expf(rmax[mt][hf] - nm);
                rmax[mt][hf] = nm;

                const int prow = R0 + mt * 16 + hf * 8;
                float ls = 0.0f;
#pragma unroll
                for (int nt = 0; nt < 8; nt++) {
                    float p0 = __expf(sacc[mt][nt][i0] - nm);
                    float p1 = __expf(sacc[mt][nt][i1] - nm);
                    ls += p0 + p1;
                    uint32_t* d = &Ps[prow * QP_STR + nt * 8 + 2 * tg];
                    d[0] = f2tf32(p0); d[1] = f2tf32(p1);
                }
                ls += __shfl_xor_sync(0xffffffffu, ls, 1);
                ls += __shfl_xor_sync(0xffffffffu, ls, 2);
                rsum[mt][hf] = rsum[mt][hf] * corr + ls;

#pragma unroll
                for (int nt = 0; nt < 8; nt++) {
                    O[mt][nt][i0] *= corr;
                    O[mt][nt][i1] *= corr;
                }
            }
        __syncwarp();

        // ---- O += P @ V ----
#pragma unroll
        for (int kk = 0; kk < 8; kk++) {
            const int kb = kk * 8;
            uint32_t a[2][4];
#pragma unroll
            for (int mt = 0; mt < 2; mt++)
                ldsm_x4(a[mt][0], a[mt][1], a[mt][2], a[mt][3],
                        Ps_sh + ((((w * 32 + mt * 16) * QP_STR) + kb) << 2) + qp_lane);
#pragma unroll
            for (int nt = 0; nt < 8; nt++) {
                uint32_t b0 = Vs[(kb + tg) * KV_STR + nt * 8 + gid];
                uint32_t b1 = Vs[(kb + tg + 4) * KV_STR + nt * 8 + gid];
                mma_tf32(O[0][nt][0], O[0][nt][1], O[0][nt][2], O[0][nt][3],
                         a[0][0], a[0][1], a[0][2], a[0][3], b0, b1);
                mma_tf32(O[1][nt][0], O[1][nt][1], O[1][nt][2], O[1][nt][3],
                         a[1][0], a[1][1], a[1][2], a[1][3], b0, b1);
            }
        }
    }

    // epilogue: normalize + store
    float* obase = out + ((size_t)b * S_LEN + qi * 128) * 1024 + h * 64;
#pragma unroll
    for (int mt = 0; mt < 2; mt++) {
        const float inv0 = 1.0f / rsum[mt][0];
        const float inv1 = 1.0f / rsum[mt][1];
        const int r = R0 + mt * 16;
#pragma unroll
        for (int nt = 0; nt < 8; nt++) {
            const int c = nt * 8 + 2 * tg;
            float2 v0, v1;
            v0.x = O[mt][nt][0] * inv0; v0.y = O[mt][nt][1] * inv0;
            v1.x = O[mt][nt][2] * inv1; v1.y = O[mt][nt][3] * inv1;
            *(float2*)(obase + (size_t)r * 1024 + c)       = v0;
            *(float2*)(obase + (size_t)(r + 8) * 1024 + c) = v1;
        }
    }
}

// ---------------------------------------------------------------------------
// Launcher
// ---------------------------------------------------------------------------
extern "C" void kernel_launch(void* const* d_in, const int* in_sizes, int n_in,
                              void* d_out, int out_size)
{
    const float* x     = (const float*)d_in[0];
    // d_in[1] = mask: deterministic causal tril -> handled analytically
    const float* Wqkv  = (const float*)d_in[2];
    const float* Wproj = (const float*)d_in[3];
    const float* bproj = (const float*)d_in[4];
    const float* Aqkv  = (const float*)d_in[5];
    const float* Bqkv  = (const float*)d_in[6];
    const float* Aproj = (const float*)d_in[7];
    const float* Bproj = (const float*)d_in[8];

    float *wq, *wp, *qkv, *att;
    cudaGetSymbolAddress((void**)&wq,  g_Wqkv);
    cudaGetSymbolAddress((void**)&wp,  g_Wproj);
    cudaGetSymbolAddress((void**)&qkv, g_qkv);
    cudaGetSymbolAddress((void**)&att, g_att);

    cudaFuncSetAttribute(attn_mma,
                         cudaFuncAttributeMaxDynamicSharedMemorySize, ATTN2_SMEM_BYTES);

    // 1) fold LoRA into dense weights
    fuse_w<<<(N_QKV * E_DIM + 255) / 256, 256>>>(Wqkv, Aqkv, Bqkv, wq, N_QKV);
    fuse_w<<<(E_DIM * E_DIM + 255) / 256, 256>>>(Wproj, Aproj, Bproj, wp, E_DIM);

    // 2) qkv = x @ Wqkv_eff^T   (tf32 tensor cores)
    gemm_mma<false><<<dim3(N_QKV / 128, M_TOK / 128), 256>>>(
        x, wq, nullptr, qkv, E_DIM, N_QKV);

    // 3) causal flash attention (tf32 tensor cores, 128-row q-tiles)
    attn_mma<<<dim3(S_LEN / 128, B_NUM * H_NUM), 128, ATTN2_SMEM_BYTES>>>(qkv, att);

    // 4) out = att @ Wproj_eff^T + bproj   (tf32 tensor cores)
    gemm_mma<true><<<dim3(E_DIM / 128, M_TOK / 128), 256>>>(
        att, wp, bproj, (float*)d_out, E_DIM, E_DIM);
}

// round 8
// speedup vs baseline: 2.9914x; 1.0324x over previous
#include <cuda_runtime.h>
#include <cstdint>

// Problem constants
#define E_DIM   1024
#define H_NUM   16
#define B_NUM   4
#define S_LEN   2048
#define R_RANK  8
#define M_TOK   (B_NUM * S_LEN)      // 8192
#define N_QKV   (3 * E_DIM)          // 3072
#define LORA_SCALING 2.0f
#define ATTN_SCALE   0.125f          // D^-0.5

// ---------------------------------------------------------------------------
// Scratch (device globals: allocation-free per harness rules)
// ---------------------------------------------------------------------------
__device__ float g_x[(size_t)M_TOK * E_DIM];     // tf32-rounded x    (32 MB)
__device__ float g_Wqkv[N_QKV * E_DIM];          // fused QKV weight  (12 MB)
__device__ float g_Wproj[E_DIM * E_DIM];         // fused proj weight (4 MB)
__device__ float g_qkv[(size_t)M_TOK * N_QKV];   // qkv activations (96 MB)
__device__ float g_att[(size_t)M_TOK * E_DIM];   // attention out   (32 MB)

// ---------------------------------------------------------------------------
// helpers
// ---------------------------------------------------------------------------
__device__ __forceinline__ uint32_t f2tf32(float f) {
    uint32_t o;
    asm("cvt.rna.tf32.f32 %0, %1;" : "=r"(o) : "f"(f));
    return o;
}
__device__ __forceinline__ float rndtf(float f) {
    return __uint_as_float(f2tf32(f));
}
__device__ __forceinline__ void mma_tf32(float& c0, float& c1, float& c2, float& c3,
                                         uint32_t a0, uint32_t a1, uint32_t a2, uint32_t a3,
                                         uint32_t b0, uint32_t b1) {
    asm volatile(
        "mma.sync.aligned.m16n8k8.row.col.f32.tf32.tf32.f32 "
        "{%0,%1,%2,%3}, {%4,%5,%6,%7}, {%8,%9}, {%0,%1,%2,%3};"
        : "+f"(c0), "+f"(c1), "+f"(c2), "+f"(c3)
        : "r"(a0), "r"(a1), "r"(a2), "r"(a3), "r"(b0), "r"(b1));
}
__device__ __forceinline__ void ldsm_x4(uint32_t& r0, uint32_t& r1,
                                        uint32_t& r2, uint32_t& r3, uint32_t addr) {
    asm volatile("ldmatrix.sync.aligned.m8n8.x4.shared.b16 {%0,%1,%2,%3}, [%4];"
                 : "=r"(r0), "=r"(r1), "=r"(r2), "=r"(r3) : "r"(addr));
}

// ---------------------------------------------------------------------------
// Kernel 0: round a tensor to tf32 (rna) once
// ---------------------------------------------------------------------------
__global__ void round_tf32(const float4* __restrict__ in, float4* __restrict__ out, int n4)
{
    int i = blockIdx.x * 256 + threadIdx.x;
    if (i >= n4) return;
    float4 v = in[i];
    v.x = rndtf(v.x); v.y = rndtf(v.y); v.z = rndtf(v.z); v.w = rndtf(v.w);
    out[i] = v;
}

// ---------------------------------------------------------------------------
// Kernel 1: fold LoRA into dense weight:  out = rna(W + 2 * (Bm @ Am))
// ---------------------------------------------------------------------------
__global__ void fuse_w(const float* __restrict__ W, const float* __restrict__ Am,
                       const float* __restrict__ Bm, float* __restrict__ out,
                       int Nrows)
{
    int idx = blockIdx.x * 256 + threadIdx.x;
    if (idx >= Nrows * 1024) return;
    int n = idx >> 10;
    int k = idx & 1023;
    float acc = W[idx];
#pragma unroll
    for (int r = 0; r < R_RANK; r++)
        acc = fmaf(LORA_SCALING * Bm[n * R_RANK + r], Am[r * 1024 + k], acc);
    out[idx] = rndtf(acc);
}

// ---------------------------------------------------------------------------
// tf32 tensor-core GEMM:  C[M,N] = A[M,K] @ W[N,K]^T (+ bias)
//   inputs pre-rounded to tf32 -> raw float4 STS, no CVT in mainloop
//   ROUND: round output to tf32 (for intermediates feeding later tf32 GEMMs)
// ---------------------------------------------------------------------------
template <bool BIAS, bool ROUND>
__global__ __launch_bounds__(256)
void gemm_mma(const float* __restrict__ A, const float* __restrict__ W,
              const float* __restrict__ bias, float* __restrict__ C,
              int Kn, int Nn)
{
    __shared__ float As[2][128][20];
    __shared__ float Ws[2][128][20];

    const int t    = threadIdx.x;
    const int wid  = t >> 5;
    const int lid  = t & 31;
    const int gid  = lid >> 2;
    const int tg   = lid & 3;
    const int wm   = (wid >> 2) * 64;
    const int wn   = (wid & 3) * 32;
    const int row0 = blockIdx.y << 7;
    const int col0 = blockIdx.x << 7;

    // ldmatrix lane addressing
    const int mh = lid >> 3;          // matrix id 0..3
    const int rr = lid & 7;
    const uint32_t As_sh = (uint32_t)__cvta_generic_to_shared(&As[0][0][0]);
    const uint32_t Ws_sh = (uint32_t)__cvta_generic_to_shared(&Ws[0][0][0]);
    const uint32_t a_lane = ((((mh & 1) * 8 + rr) * 20 + (mh >> 1) * 4) << 2);
    const uint32_t b_lane = ((((mh >> 1) * 8 + rr) * 20 + (mh & 1) * 4) << 2);

    const int lr = t >> 2;
    const int lk = (t & 3) << 2;
    const float* Ap0 = A + (size_t)(row0 + lr) * Kn + lk;
    const float* Ap1 = Ap0 + (size_t)64 * Kn;
    const float* Wp0 = W + (size_t)(col0 + lr) * Kn + lk;
    const float* Wp1 = Wp0 + (size_t)64 * Kn;

    float acc[4][4][4];
#pragma unroll
    for (int i = 0; i < 4; i++)
#pragma unroll
        for (int j = 0; j < 4; j++)
#pragma unroll
            for (int r = 0; r < 4; r++) acc[i][j][r] = 0.0f;

    const int nkt = Kn >> 4;

    {
        *(float4*)&As[0][lr][lk]      = *(const float4*)(Ap0);
        *(float4*)&As[0][lr + 64][lk] = *(const float4*)(Ap1);
        *(float4*)&Ws[0][lr][lk]      = *(const float4*)(Wp0);
        *(float4*)&Ws[0][lr + 64][lk] = *(const float4*)(Wp1);
    }
    __syncthreads();

    for (int kt = 0; kt < nkt; kt++) {
        const int cur = kt & 1, nxt = cur ^ 1;

        float4 pa0, pa1, pw0, pw1;
        if (kt + 1 < nkt) {
            const int k0 = (kt + 1) << 4;
            pa0 = *(const float4*)(Ap0 + k0);
            pa1 = *(const float4*)(Ap1 + k0);
            pw0 = *(const float4*)(Wp0 + k0);
            pw1 = *(const float4*)(Wp1 + k0);
        }

#pragma unroll
        for (int kc = 0; kc < 16; kc += 8) {
            uint32_t af[4][4], bf[4][2];
#pragma unroll
            for (int mt = 0; mt < 4; mt++)
                ldsm_x4(af[mt][0], af[mt][1], af[mt][2], af[mt][3],
                        As_sh + ((((cur * 128 + wm + mt * 16) * 20) + kc) << 2) + a_lane);
#pragma unroll
            for (int p = 0; p < 2; p++)
                ldsm_x4(bf[2*p][0], bf[2*p][1], bf[2*p+1][0], bf[2*p+1][1],
                        Ws_sh + ((((cur * 128 + wn + p * 16) * 20) + kc) << 2) + b_lane);
#pragma unroll
            for (int mt = 0; mt < 4; mt++)
#pragma unroll
                for (int nt = 0; nt < 4; nt++)
                    mma_tf32(acc[mt][nt][0], acc[mt][nt][1],
                             acc[mt][nt][2], acc[mt][nt][3],
                             af[mt][0], af[mt][1], af[mt][2], af[mt][3],
                             bf[nt][0], bf[nt][1]);
        }

        if (kt + 1 < nkt) {
            *(float4*)&As[nxt][lr][lk]      = pa0;
            *(float4*)&As[nxt][lr + 64][lk] = pa1;
            *(float4*)&Ws[nxt][lr][lk]      = pw0;
            *(float4*)&Ws[nxt][lr + 64][lk] = pw1;
        }
        __syncthreads();
    }

#pragma unroll
    for (int mt = 0; mt < 4; mt++) {
        const int r = row0 + wm + mt * 16 + gid;
#pragma unroll
        for (int nt = 0; nt < 4; nt++) {
            const int c = col0 + wn + nt * 8 + tg * 2;
            float2 v0, v1;
            v0.x = acc[mt][nt][0]; v0.y = acc[mt][nt][1];
            v1.x = acc[mt][nt][2]; v1.y = acc[mt][nt][3];
            if (BIAS) {
                float b0 = bias[c], b1 = bias[c + 1];
                v0.x += b0; v0.y += b1;
                v1.x += b0; v1.y += b1;
            }
            if (ROUND) {
                v0.x = rndtf(v0.x); v0.y = rndtf(v0.y);
                v1.x = rndtf(v1.x); v1.y = rndtf(v1.y);
            }
            *(float2*)(&C[(size_t)r * Nn + c])       = v0;
            *(float2*)(&C[(size_t)(r + 8) * Nn + c]) = v1;
        }
    }
}

// ---------------------------------------------------------------------------
// Kernel 3: causal flash attention on tensor cores (tf32 mma, fp32 softmax)
//   128 threads (4 warps); q-tile 128 rows; warp w owns q-rows [32w, 32w+32)
//   qkv input pre-rounded tf32 -> raw STS (Q scaled by exact 2^-3)
//   Q/P (q,k-major) + K (k,d natural) via ldmatrix
//   V stored TRANSPOSED Vt[d][k] with 32B XOR swizzle -> PV B-frags via ldmatrix
// ---------------------------------------------------------------------------
#define QP_STR 68
#define KV_STR 68
#define ATTN2_SMEM_BYTES ((128*QP_STR*2 + 64*KV_STR*2) * 4)   // 104448

__global__ __launch_bounds__(128)
void attn_mma(const float* __restrict__ qkv, float* __restrict__ out)
{
    extern __shared__ uint32_t smu[];
    uint32_t* Qs = smu;                      // [128][QP_STR]
    uint32_t* Ps = Qs + 128 * QP_STR;        // [128][QP_STR]
    uint32_t* Ks = Ps + 128 * QP_STR;        // [64][KV_STR]  (k,d) natural
    uint32_t* Vt = Ks + 64 * KV_STR;         // [64][KV_STR]  (d,k) swizzled

    const int t   = threadIdx.x;
    const int w   = t >> 5;                  // 0..3
    const int lid = t & 31;
    const int gid = lid >> 2;
    const int tg  = lid & 3;

    // ldmatrix lane addressing
    const int mh = lid >> 3;
    const int rr = lid & 7;
    const uint32_t Qs_sh = (uint32_t)__cvta_generic_to_shared(Qs);
    const uint32_t Ps_sh = (uint32_t)__cvta_generic_to_shared(Ps);
    const uint32_t Ks_sh = (uint32_t)__cvta_generic_to_shared(Ks);
    const uint32_t Vt_sh = (uint32_t)__cvta_generic_to_shared(Vt);
    const uint32_t qp_lane = ((((mh & 1) * 8 + rr) * QP_STR + (mh >> 1) * 4) << 2);
    const uint32_t kb_lane = ((((mh >> 1) * 8 + rr) * KV_STR + (mh & 1) * 4) << 2);
    const int rbv = (mh >> 1) * 8 + rr;      // Vt row within 16-block
    const int cbv = (mh & 1) * 4;            // Vt 16B-chunk word offset

    const int qi = (int)gridDim.x - 1 - (int)blockIdx.x;  // long blocks first
    const int bh = blockIdx.y;
    const int b  = bh >> 4;
    const int h  = bh & 15;

    const float* qbase = qkv + (size_t)b * S_LEN * 3072 + h * 64;
    const float* kbase = qbase + 1024;
    const float* vbase = qbase + 2048;

    const int lr = t >> 4;            // 0..7
    const int dd = (t & 15) * 4;      // 0..60
    const int vq = (dd >> 3) & 3;     // Vt swizzle term (constant per thread)

    // load Q tile (128 rows; inputs pre-rounded; *2^-3 exact; raw store)
    {
        const float* qp = qbase + (size_t)(qi * 128 + lr) * 3072 + dd;
#pragma unroll
        for (int p = 0; p < 16; p++) {
            int r = lr + p * 8;
            float4 q4 = *(const float4*)(qp + (size_t)(p * 8) * 3072);
            uint4 u;
            u.x = __float_as_uint(q4.x * ATTN_SCALE);
            u.y = __float_as_uint(q4.y * ATTN_SCALE);
            u.z = __float_as_uint(q4.z * ATTN_SCALE);
            u.w = __float_as_uint(q4.w * ATTN_SCALE);
            *(uint4*)&Qs[r * QP_STR + dd] = u;
        }
    }

    const int R0 = w * 32 + gid;      // warp rows: R0, R0+8, R0+16, R0+24
    float O[2][8][4];
    float rmax[2][2], rsum[2][2];
#pragma unroll
    for (int mt = 0; mt < 2; mt++) {
        rmax[mt][0] = -1e30f; rmax[mt][1] = -1e30f;
        rsum[mt][0] = 0.0f;   rsum[mt][1] = 0.0f;
#pragma unroll
        for (int nt = 0; nt < 8; nt++)
#pragma unroll
            for (int r = 0; r < 4; r++) O[mt][nt][r] = 0.0f;
    }

    const int jmax = 2 * qi + 1;
    for (int j = 0; j <= jmax; j++) {
        __syncthreads();   // prior compute done reading Ks/Vt (covers Q on j=0)

        // load K ([k][d] natural, raw uint4) and V (transposed+swizzled)
        const float* kp = kbase + (size_t)(j * 64 + lr) * 3072 + dd;
        const float* vp = vbase + (size_t)(j * 64 + lr) * 3072 + dd;
#pragma unroll
        for (int p = 0; p < 8; p++) {
            int r = lr + p * 8;
            float4 k4 = *(const float4*)(kp + (size_t)(p * 8) * 3072);
            uint4 uk;
            uk.x = __float_as_uint(k4.x); uk.y = __float_as_uint(k4.y);
            uk.z = __float_as_uint(k4.z); uk.w = __float_as_uint(k4.w);
            *(uint4*)&Ks[r * KV_STR + dd] = uk;
            float4 v4 = *(const float4*)(vp + (size_t)(p * 8) * 3072);
            const int wcol = (((r >> 3) ^ vq) << 3) + (r & 7);
            Vt[(dd + 0) * KV_STR + wcol] = __float_as_uint(v4.x);
            Vt[(dd + 1) * KV_STR + wcol] = __float_as_uint(v4.y);
            Vt[(dd + 2) * KV_STR + wcol] = __float_as_uint(v4.z);
            Vt[(dd + 3) * KV_STR + wcol] = __float_as_uint(v4.w);
        }
        __syncthreads();

        // warp fully masked? (all cols > all rows)
        if (j * 64 > qi * 128 + w * 32 + 31) continue;

        // ---- S = Q @ K^T ----
        float sacc[2][8][4];
#pragma unroll
        for (int mt = 0; mt < 2; mt++)
#pragma unroll
            for (int nt = 0; nt < 8; nt++)
#pragma unroll
                for (int r = 0; r < 4; r++) sacc[mt][nt][r] = 0.0f;

#pragma unroll
        for (int kk = 0; kk < 8; kk++) {
            const int kb = kk * 8;
            uint32_t a[2][4], bk[8][2];
#pragma unroll
            for (int mt = 0; mt < 2; mt++)
                ldsm_x4(a[mt][0], a[mt][1], a[mt][2], a[mt][3],
                        Qs_sh + ((((w * 32 + mt * 16) * QP_STR) + kb) << 2) + qp_lane);
#pragma unroll
            for (int p = 0; p < 4; p++)
                ldsm_x4(bk[2*p][0], bk[2*p][1], bk[2*p+1][0], bk[2*p+1][1],
                        Ks_sh + ((((p * 16) * KV_STR) + kb) << 2) + kb_lane);
#pragma unroll
            for (int nt = 0; nt < 8; nt++) {
                mma_tf32(sacc[0][nt][0], sacc[0][nt][1], sacc[0][nt][2], sacc[0][nt][3],
                         a[0][0], a[0][1], a[0][2], a[0][3], bk[nt][0], bk[nt][1]);
                mma_tf32(sacc[1][nt][0], sacc[1][nt][1], sacc[1][nt][2], sacc[1][nt][3],
                         a[1][0], a[1][1], a[1][2], a[1][3], bk[nt][0], bk[nt][1]);
            }
        }

        // causal mask (only when tile straddles this warp's diagonal range)
        if (j * 64 + 63 > qi * 128 + w * 32) {
#pragma unroll
            for (int mt = 0; mt < 2; mt++) {
                const int rg0 = qi * 128 + R0 + mt * 16;
                const int rg1 = rg0 + 8;
#pragma unroll
                for (int nt = 0; nt < 8; nt++) {
                    const int cg = j * 64 + nt * 8 + 2 * tg;
                    if (cg     > rg0) sacc[mt][nt][0] = -1e30f;
                    if (cg + 1 > rg0) sacc[mt][nt][1] = -1e30f;
                    if (cg     > rg1) sacc[mt][nt][2] = -1e30f;
                    if (cg + 1 > rg1) sacc[mt][nt][3] = -1e30f;
                }
            }
        }

        // ---- online softmax (4 rows per thread) ----
#pragma unroll
        for (int mt = 0; mt < 2; mt++)
#pragma unroll
            for (int hf = 0; hf < 2; hf++) {
                const int i0 = hf * 2, i1 = hf * 2 + 1;
                float m = -1e30f;
#pragma unroll
                for (int nt = 0; nt < 8; nt++)
                    m = fmaxf(m, fmaxf(sacc[mt][nt][i0], sacc[mt][nt][i1]));
                m = fmaxf(m, __shfl_xor_sync(0xffffffffu, m, 1));
                m = fmaxf(m, __shfl_xor_sync(0xffffffffu, m, 2));

                float nm = fmaxf(rmax[mt][hf], m);
                float corr = __expf(rmax[mt][hf] - nm);
                rmax[mt][hf] = nm;

                const int prow = R0 + mt * 16 + hf * 8;
                float ls = 0.0f;
#pragma unroll
                for (int nt = 0; nt < 8; nt++) {
                    float p0 = __expf(sacc[mt][nt][i0] - nm);
                    float p1 = __expf(sacc[mt][nt][i1] - nm);
                    ls += p0 + p1;
                    uint32_t* d = &Ps[prow * QP_STR + nt * 8 + 2 * tg];
                    d[0] = f2tf32(p0); d[1] = f2tf32(p1);
                }
                ls += __shfl_xor_sync(0xffffffffu, ls, 1);
                ls += __shfl_xor_sync(0xffffffffu, ls, 2);
                rsum[mt][hf] = rsum[mt][hf] * corr + ls;

#pragma unroll
                for (int nt = 0; nt < 8; nt++) {
                    O[mt][nt][i0] *= corr;
                    O[mt][nt][i1] *= corr;
                }
            }
        __syncwarp();

        // ---- O += P @ V : B-frags from swizzled Vt via ldmatrix ----
#pragma unroll
        for (int kk = 0; kk < 8; kk++) {
            const int kb = kk * 8;
            uint32_t a[2][4], bv[8][2];
#pragma unroll
            for (int mt = 0; mt < 2; mt++)
                ldsm_x4(a[mt][0], a[mt][1], a[mt][2], a[mt][3],
                        Ps_sh + ((((w * 32 + mt * 16) * QP_STR) + kb) << 2) + qp_lane);
#pragma unroll
            for (int p = 0; p < 4; p++) {
                const int R  = p * 16 + rbv;
                const int Rq = (p * 2 + (mh >> 1)) & 3;
                const uint32_t addr =
                    Vt_sh + ((R * KV_STR + ((kk ^ Rq) << 3) + cbv) << 2);
                ldsm_x4(bv[2*p][0], bv[2*p][1], bv[2*p+1][0], bv[2*p+1][1], addr);
            }
#pragma unroll
            for (int nt = 0; nt < 8; nt++) {
                mma_tf32(O[0][nt][0], O[0][nt][1], O[0][nt][2], O[0][nt][3],
                         a[0][0], a[0][1], a[0][2], a[0][3], bv[nt][0], bv[nt][1]);
                mma_tf32(O[1][nt][0], O[1][nt][1], O[1][nt][2], O[1][nt][3],
                         a[1][0], a[1][1], a[1][2], a[1][3], bv[nt][0], bv[nt][1]);
            }
        }
    }

    // epilogue: normalize + round to tf32 (feeds proj GEMM) + store
    float* obase = out + ((size_t)b * S_LEN + qi * 128) * 1024 + h * 64;
#pragma unroll
    for (int mt = 0; mt < 2; mt++) {
        const float inv0 = 1.0f / rsum[mt][0];
        const float inv1 = 1.0f / rsum[mt][1];
        const int r = R0 + mt * 16;
#pragma unroll
        for (int nt = 0; nt < 8; nt++) {
            const int c = nt * 8 + 2 * tg;
            float2 v0, v1;
            v0.x = rndtf(O[mt][nt][0] * inv0); v0.y = rndtf(O[mt][nt][1] * inv0);
            v1.x = rndtf(O[mt][nt][2] * inv1); v1.y = rndtf(O[mt][nt][3] * inv1);
            *(float2*)(obase + (size_t)r * 1024 + c)       = v0;
            *(float2*)(obase + (size_t)(r + 8) * 1024 + c) = v1;
        }
    }
}

// ---------------------------------------------------------------------------
// Launcher
// ---------------------------------------------------------------------------
extern "C" void kernel_launch(void* const* d_in, const int* in_sizes, int n_in,
                              void* d_out, int out_size)
{
    const float* x     = (const float*)d_in[0];
    // d_in[1] = mask: deterministic causal tril -> handled analytically
    const float* Wqkv  = (const float*)d_in[2];
    const float* Wproj = (const float*)d_in[3];
    const float* bproj = (const float*)d_in[4];
    const float* Aqkv  = (const float*)d_in[5];
    const float* Bqkv  = (const float*)d_in[6];
    const float* Aproj = (const float*)d_in[7];
    const float* Bproj = (const float*)d_in[8];

    float *gx, *wq, *wp, *qkv, *att;
    cudaGetSymbolAddress((void**)&gx,  g_x);
    cudaGetSymbolAddress((void**)&wq,  g_Wqkv);
    cudaGetSymbolAddress((void**)&wp,  g_Wproj);
    cudaGetSymbolAddress((void**)&qkv, g_qkv);
    cudaGetSymbolAddress((void**)&att, g_att);

    cudaFuncSetAttribute(attn_mma,
                         cudaFuncAttributeMaxDynamicSharedMemorySize, ATTN2_SMEM_BYTES);

    // 0) round x to tf32 once
    const int n4 = M_TOK * E_DIM / 4;
    round_tf32<<<(n4 + 255) / 256, 256>>>((const float4*)x, (float4*)gx, n4);

    // 1) fold LoRA into dense weights (tf32-rounded)
    fuse_w<<<(N_QKV * E_DIM + 255) / 256, 256>>>(Wqkv, Aqkv, Bqkv, wq, N_QKV);
    fuse_w<<<(E_DIM * E_DIM + 255) / 256, 256>>>(Wproj, Aproj, Bproj, wp, E_DIM);

    // 2) qkv = x @ Wqkv_eff^T   (tf32 TC; output rounded for attention)
    gemm_mma<false, true><<<dim3(N_QKV / 128, M_TOK / 128), 256>>>(
        gx, wq, nullptr, qkv, E_DIM, N_QKV);

    // 3) causal flash attention (tf32 TC; output rounded for proj GEMM)
    attn_mma<<<dim3(S_LEN / 128, B_NUM * H_NUM), 128, ATTN2_SMEM_BYTES>>>(qkv, att);

    // 4) out = att @ Wproj_eff^T + bproj   (tf32 TC, full fp32 output)
    gemm_mma<true, false><<<dim3(E_DIM / 128, M_TOK / 128), 256>>>(
        att, wp, bproj, (float*)d_out, E_DIM, E_DIM);
}